// round 5
// baseline (speedup 1.0000x reference)
#include <cuda_runtime.h>
#include <cuda_bf16.h>
#include <math.h>
#include <stdint.h>

typedef __nv_bfloat16 bf16;

// ---------------------------------------------------------------- constants
#define LSEQ 1024
#define DIM  256
#define BH   32          // B*N heads
#define EDGE_C 112
#define KAPPA 10000.0f

#define H_ELEMS  (BH * LSEQ * DIM)
#define X_ELEMS  (BH * LSEQ * 3)
#define E_ELEMS  (4 * LSEQ * EDGE_C)
#define X_OFF    H_ELEMS
#define E_OFF    (H_ELEMS + X_ELEMS)

// ---------------------------------------------------------------- scratch
__device__ __align__(16) bf16 g_TPh[H_ELEMS], g_TPl[H_ELEMS];
__device__ __align__(16) bf16 g_Wh[3 * DIM * DIM], g_Wl[3 * DIM * DIM];
__device__ __align__(16) bf16 g_Qh[H_ELEMS], g_Ql[H_ELEMS];
__device__ __align__(16) bf16 g_Kh[H_ELEMS], g_Kl[H_ELEMS];
__device__ __align__(16) bf16 g_Vh[H_ELEMS], g_Vl[H_ELEMS];
__device__ __align__(16) bf16 g_VTh[H_ELEMS], g_VTl[H_ELEMS];      // [bh][e][s]
__device__ __align__(16) float g_S[(size_t)BH * LSEQ * LSEQ];

__device__ __forceinline__ void split2(float v, bf16& h, bf16& l) {
    h = __float2bfloat16(v);
    l = __float2bfloat16(v - __bfloat162float(h));
}

// ---------------------------------------------------------------- MMA core
#define MMA(acc, af, bf)                                                        \
    asm volatile(                                                               \
        "mma.sync.aligned.m16n8k16.row.col.f32.bf16.bf16.f32 "                  \
        "{%0,%1,%2,%3}, {%4,%5,%6,%7}, {%8,%9}, {%0,%1,%2,%3};"                 \
        : "+f"((acc)[0]), "+f"((acc)[1]), "+f"((acc)[2]), "+f"((acc)[3])        \
        : "r"((af)[0]), "r"((af)[1]), "r"((af)[2]), "r"((af)[3]),               \
          "r"((bf)[0]), "r"((bf)[1]))

#define KPAD 40   // 32 k + 8 pad: 80B row stride (16B aligned for cp.async)

struct Stage {
    bf16 Ah[128][KPAD], Al[128][KPAD], Bh[128][KPAD], Bl[128][KPAD];
};
#define SMEM_DYN (2 * sizeof(Stage))   // 81920 B

__device__ __forceinline__ void cp16(void* dst, const void* src) {
    uint32_t d = (uint32_t)__cvta_generic_to_shared(dst);
    asm volatile("cp.async.cg.shared.global [%0], [%1], 16;" :: "r"(d), "l"(src));
}
#define CP_COMMIT() asm volatile("cp.async.commit_group;" ::: "memory")
#define CP_WAIT1()  asm volatile("cp.async.wait_group 1;" ::: "memory")
#define CP_WAIT0()  asm volatile("cp.async.wait_group 0;" ::: "memory")

// Async-stage one 128x32 bf16 slice (256 threads, 2 x 16B each).
#define LDTA(SM, GP, LD) do {                                                   \
    int _r = tid >> 2, _c = (tid & 3) * 8;                                      \
    cp16(&SM[_r][_c],      (GP) + (size_t)_r * (LD) + _c);                      \
    cp16(&SM[_r + 64][_c], (GP) + (size_t)(_r + 64) * (LD) + _c);               \
} while (0)

#define LDSTAGE(ST, K0) do {                                                    \
    LDTA((ST).Ah, Agh + (K0), lda);                                             \
    LDTA((ST).Al, Agl + (K0), lda);                                             \
    LDTA((ST).Bh, Bgh + (K0), ldb);                                             \
    LDTA((ST).Bl, Bgl + (K0), ldb);                                             \
    CP_COMMIT();                                                                \
} while (0)

// Block tile 128x128, 8 warps (2m x 4n), warp tile 64x32, K-step 32,
// cp.async double-buffered.  3-pass hi/lo split.
__device__ __forceinline__ void gemm_main(
    Stage* stg,
    const bf16* __restrict__ Agh, const bf16* __restrict__ Agl, int lda,
    const bf16* __restrict__ Bgh, const bf16* __restrict__ Bgl, int ldb,
    int K, float acc[4][4][4], int tid)
{
    int wid = tid >> 5, lane = tid & 31;
    int wm = (wid >> 2) * 64, wn = (wid & 3) * 32;
    int gr = lane >> 2, t4 = lane & 3;
    int nst = K >> 5;

    LDSTAGE(stg[0], 0);

    for (int c = 0; c < nst; c++) {
        if (c + 1 < nst) { LDSTAGE(stg[(c + 1) & 1], (c + 1) * 32); CP_WAIT1(); }
        else             { CP_WAIT0(); }
        __syncthreads();
        Stage& s = stg[c & 1];
        #pragma unroll
        for (int kk = 0; kk < 32; kk += 16) {
            uint32_t Afh[4][4], Afl[4][4], Bfh[4][2], Bfl[4][2];
            #pragma unroll
            for (int mt = 0; mt < 4; mt++) {
                int r = wm + mt * 16 + gr, cc = kk + 2 * t4;
                Afh[mt][0] = *(const uint32_t*)&s.Ah[r][cc];
                Afh[mt][1] = *(const uint32_t*)&s.Ah[r + 8][cc];
                Afh[mt][2] = *(const uint32_t*)&s.Ah[r][cc + 8];
                Afh[mt][3] = *(const uint32_t*)&s.Ah[r + 8][cc + 8];
                Afl[mt][0] = *(const uint32_t*)&s.Al[r][cc];
                Afl[mt][1] = *(const uint32_t*)&s.Al[r + 8][cc];
                Afl[mt][2] = *(const uint32_t*)&s.Al[r][cc + 8];
                Afl[mt][3] = *(const uint32_t*)&s.Al[r + 8][cc + 8];
            }
            #pragma unroll
            for (int nt = 0; nt < 4; nt++) {
                int n = wn + nt * 8 + gr, cc = kk + 2 * t4;
                Bfh[nt][0] = *(const uint32_t*)&s.Bh[n][cc];
                Bfh[nt][1] = *(const uint32_t*)&s.Bh[n][cc + 8];
                Bfl[nt][0] = *(const uint32_t*)&s.Bl[n][cc];
                Bfl[nt][1] = *(const uint32_t*)&s.Bl[n][cc + 8];
            }
            #pragma unroll
            for (int mt = 0; mt < 4; mt++)
                #pragma unroll
                for (int nt = 0; nt < 4; nt++) {
                    MMA(acc[mt][nt], Afh[mt], Bfh[nt]);
                    MMA(acc[mt][nt], Afh[mt], Bfl[nt]);
                    MMA(acc[mt][nt], Afl[mt], Bfh[nt]);
                }
        }
        __syncthreads();
    }
}

// ---------------------------------------------------------------- prep
__global__ void k_prep_w(const float* __restrict__ Wq, const float* __restrict__ Wk,
                         const float* __restrict__ Wv) {
    int idx = blockIdx.x * 256 + threadIdx.x;
    int mat = idx >> 16, off = idx & 65535;
    const float* W = (mat == 0) ? Wq : (mat == 1) ? Wk : Wv;
    split2(W[off], g_Wh[idx], g_Wl[idx]);
}

__global__ void k_theta_pe(const float* __restrict__ theta) {
    int idx = blockIdx.x * 256 + threadIdx.x;
    int i = idx & (DIM - 1);
    int l = (idx >> 8) & (LSEQ - 1);
    float expo = (float)(i & ~1) * (1.0f / (float)DIM);
    float ang = (float)l / powf(KAPPA, expo);
    float pe = (i & 1) ? cosf(ang) : sinf(ang);
    split2(theta[idx] + pe, g_TPh[idx], g_TPl[idx]);
}

// ---------------------------------------------------------------- QKV
__global__ void __launch_bounds__(256) k_qkv_mma() {
    extern __shared__ char smraw[];
    Stage* stg = reinterpret_cast<Stage*>(smraw);
    int tid = threadIdx.x;
    int e0 = blockIdx.x * 128, m0 = blockIdx.y * 128, mat = blockIdx.z;

    float acc[4][4][4] = {};
    gemm_main(stg, g_TPh + (size_t)m0 * DIM, g_TPl + (size_t)m0 * DIM, DIM,
              g_Wh + (size_t)mat * 65536 + (size_t)e0 * DIM,
              g_Wl + (size_t)mat * 65536 + (size_t)e0 * DIM, DIM,
              DIM, acc, tid);

    bf16 *oh, *ol;
    if (mat == 0)      { oh = g_Qh; ol = g_Ql; }
    else if (mat == 1) { oh = g_Kh; ol = g_Kl; }
    else               { oh = g_Vh; ol = g_Vl; }
    int wid = tid >> 5, lane = tid & 31;
    int wm = (wid >> 2) * 64, wn = (wid & 3) * 32;
    int gr = lane >> 2, t4 = lane & 3;
    #pragma unroll
    for (int mt = 0; mt < 4; mt++)
        #pragma unroll
        for (int nt = 0; nt < 4; nt++)
            #pragma unroll
            for (int half = 0; half < 2; half++) {
                int r = m0 + wm + mt * 16 + gr + half * 8;
                int c = e0 + wn + nt * 8 + 2 * t4;
                __nv_bfloat162 h2, l2;
                split2(acc[mt][nt][half * 2],     h2.x, l2.x);
                split2(acc[mt][nt][half * 2 + 1], h2.y, l2.y);
                *(uint32_t*)&oh[(size_t)r * DIM + c] = *(uint32_t*)&h2;
                *(uint32_t*)&ol[(size_t)r * DIM + c] = *(uint32_t*)&l2;
            }
}

// ---------------------------------------------------------------- V transpose
__global__ void k_vt() {
    __shared__ bf16 th[32][33], tl[32][33];
    int s0 = blockIdx.x * 32, e0 = blockIdx.y * 32, bh = blockIdx.z;
    int tx = threadIdx.x, ty = threadIdx.y;
    #pragma unroll
    for (int j = 0; j < 4; j++) {
        int sr = s0 + ty + j * 8;
        size_t src = ((size_t)bh * LSEQ + sr) * DIM + e0 + tx;
        th[ty + j * 8][tx] = g_Vh[src];
        tl[ty + j * 8][tx] = g_Vl[src];
    }
    __syncthreads();
    #pragma unroll
    for (int j = 0; j < 4; j++) {
        int e = e0 + ty + j * 8;
        size_t dst = ((size_t)bh * DIM + e) * LSEQ + s0 + tx;
        g_VTh[dst] = th[tx][ty + j * 8];
        g_VTl[dst] = tl[tx][ty + j * 8];
    }
}

// ---------------------------------------------------------------- scores
__global__ void __launch_bounds__(256) k_scores_mma() {
    int kt = blockIdx.x, qt = blockIdx.y, bh = blockIdx.z;
    if (kt > qt) return;
    extern __shared__ char smraw[];
    Stage* stg = reinterpret_cast<Stage*>(smraw);
    int tid = threadIdx.x;
    int q0 = qt * 128, c0 = kt * 128;
    size_t qb = ((size_t)bh * LSEQ + q0) * DIM;
    size_t kb = ((size_t)bh * LSEQ + c0) * DIM;

    float acc[4][4][4] = {};
    gemm_main(stg, g_Qh + qb, g_Ql + qb, DIM, g_Kh + kb, g_Kl + kb, DIM,
              DIM, acc, tid);

    int wid = tid >> 5, lane = tid & 31;
    int wm = (wid >> 2) * 64, wn = (wid & 3) * 32;
    int gr = lane >> 2, t4 = lane & 3;
    float* S = g_S + (size_t)bh * LSEQ * LSEQ;
    #pragma unroll
    for (int mt = 0; mt < 4; mt++)
        #pragma unroll
        for (int nt = 0; nt < 4; nt++)
            #pragma unroll
            for (int half = 0; half < 2; half++) {
                int r = q0 + wm + mt * 16 + gr + half * 8;
                int c = c0 + wn + nt * 8 + 2 * t4;
                float2 v = make_float2(acc[mt][nt][half * 2] * 0.0625f,
                                       acc[mt][nt][half * 2 + 1] * 0.0625f);
                *(float2*)&S[(size_t)r * LSEQ + c] = v;
            }
}

// ---------------------------------------------------------------- fused softmax+PV
// Per block (qt, bh): online softmax over kt tiles of S (gmem), P kept in
// smem only, O accumulated in registers (128q x 256e over 8 warps).
struct SvSmem {
    union {
        float Ss[128][132];                       // S tile stage (fp32)
        struct { bf16 h[128][136]; bf16 l[128][136]; } B;  // VT tile stage
    } u;
    bf16 Ph[128][136], Pl[128][136];              // P tile (hi/lo)
    float mrow[128], lrow[128], frow[128];
};
#define SV_SMEM sizeof(SvSmem)

__global__ void __launch_bounds__(256) k_sv(float* __restrict__ out) {
    extern __shared__ char smraw[];
    SvSmem& sm = *reinterpret_cast<SvSmem*>(smraw);
    int tid = threadIdx.x, wid = tid >> 5, lane = tid & 31;
    int qt = 7 - blockIdx.x, bh = blockIdx.y;     // heavy blocks first
    int q0 = qt * 128;
    int wm = (wid >> 2) * 64, wn = (wid & 3) * 32;
    int gr = lane >> 2, t4 = lane & 3;
    const float* Sbase = g_S + (size_t)bh * LSEQ * LSEQ + (size_t)q0 * LSEQ;

    if (tid < 128) { sm.mrow[tid] = -1e30f; sm.lrow[tid] = 0.0f; }
    float acc[2][4][4][4] = {};                   // [e-half][mt][nt][frag]
    int r2 = tid >> 1, half = tid & 1;            // softmax: 2 thr per row
    int cb = half * 64;

    for (int kt = 0; kt <= qt; kt++) {
        __syncthreads();                          // union reuse / stats init
        // ---- stage S tile (128x128 f32)
        #pragma unroll
        for (int i = 0; i < 16; i++) {
            int u = i * 256 + tid, r = u >> 5, c = u & 31;
            cp16(&sm.u.Ss[r][c * 4], Sbase + (size_t)r * LSEQ + kt * 128 + c * 4);
        }
        CP_COMMIT(); CP_WAIT0();
        __syncthreads();
        // ---- online softmax for 64 cols of one row
        bool diag = (kt == qt);
        float mloc = -1e30f;
        #pragma unroll
        for (int j = 0; j < 64; j++) {
            float s = sm.u.Ss[r2][cb + j];
            if (diag && (cb + j > r2)) s = -1e30f;
            mloc = fmaxf(mloc, s);
        }
        mloc = fmaxf(mloc, __shfl_xor_sync(0xFFFFFFFFu, mloc, 1));
        float mold = sm.mrow[r2];
        float mnew = fmaxf(mold, mloc);
        float fac = expf(mold - mnew);
        float ssum = 0.0f;
        #pragma unroll
        for (int j = 0; j < 64; j += 2) {
            float s0 = sm.u.Ss[r2][cb + j];
            float s1 = sm.u.Ss[r2][cb + j + 1];
            bool v0 = !diag || (cb + j     <= r2);
            bool v1 = !diag || (cb + j + 1 <= r2);
            float p0 = v0 ? expf(s0 - mnew) : 0.0f;
            float p1 = v1 ? expf(s1 - mnew) : 0.0f;
            ssum += p0 + p1;
            __nv_bfloat162 h2, l2;
            split2(p0, h2.x, l2.x); split2(p1, h2.y, l2.y);
            *(uint32_t*)&sm.Ph[r2][cb + j] = *(uint32_t*)&h2;
            *(uint32_t*)&sm.Pl[r2][cb + j] = *(uint32_t*)&l2;
        }
        ssum += __shfl_xor_sync(0xFFFFFFFFu, ssum, 1);
        if (!half) {
            sm.mrow[r2] = mnew;
            sm.lrow[r2] = sm.lrow[r2] * fac + ssum;
            sm.frow[r2] = fac;
        }
        __syncthreads();
        // ---- rescale O accumulator
        #pragma unroll
        for (int mt = 0; mt < 4; mt++) {
            float f0 = sm.frow[wm + mt * 16 + gr];
            float f1 = sm.frow[wm + mt * 16 + gr + 8];
            #pragma unroll
            for (int h = 0; h < 2; h++)
                #pragma unroll
                for (int nt = 0; nt < 4; nt++) {
                    acc[h][mt][nt][0] *= f0; acc[h][mt][nt][1] *= f0;
                    acc[h][mt][nt][2] *= f1; acc[h][mt][nt][3] *= f1;
                }
        }
        // ---- PV MMA per e-half (B tile 128e x 128k hi/lo from g_VT)
        #pragma unroll
        for (int h = 0; h < 2; h++) {
            __syncthreads();                      // Ss dead / prev half done
            const bf16* vth = g_VTh + ((size_t)bh * DIM + h * 128) * LSEQ + kt * 128;
            const bf16* vtl = g_VTl + ((size_t)bh * DIM + h * 128) * LSEQ + kt * 128;
            #pragma unroll
            for (int i = 0; i < 8; i++) {
                int u = i * 256 + tid, r = (u >> 4) & 127, c = u & 15;
                cp16(&sm.u.B.h[r][c * 8], vth + (size_t)r * LSEQ + c * 8);
                cp16(&sm.u.B.l[r][c * 8], vtl + (size_t)r * LSEQ + c * 8);
            }
            CP_COMMIT(); CP_WAIT0();
            __syncthreads();
            #pragma unroll
            for (int kk = 0; kk < 128; kk += 16) {
                uint32_t Afh[4][4], Afl[4][4], Bfh[4][2], Bfl[4][2];
                #pragma unroll
                for (int mt = 0; mt < 4; mt++) {
                    int r = wm + mt * 16 + gr, cc = kk + 2 * t4;
                    Afh[mt][0] = *(const uint32_t*)&sm.Ph[r][cc];
                    Afh[mt][1] = *(const uint32_t*)&sm.Ph[r + 8][cc];
                    Afh[mt][2] = *(const uint32_t*)&sm.Ph[r][cc + 8];
                    Afh[mt][3] = *(const uint32_t*)&sm.Ph[r + 8][cc + 8];
                    Afl[mt][0] = *(const uint32_t*)&sm.Pl[r][cc];
                    Afl[mt][1] = *(const uint32_t*)&sm.Pl[r + 8][cc];
                    Afl[mt][2] = *(const uint32_t*)&sm.Pl[r][cc + 8];
                    Afl[mt][3] = *(const uint32_t*)&sm.Pl[r + 8][cc + 8];
                }
                #pragma unroll
                for (int nt = 0; nt < 4; nt++) {
                    int n = wn + nt * 8 + gr, cc = kk + 2 * t4;
                    Bfh[nt][0] = *(const uint32_t*)&sm.u.B.h[n][cc];
                    Bfh[nt][1] = *(const uint32_t*)&sm.u.B.h[n][cc + 8];
                    Bfl[nt][0] = *(const uint32_t*)&sm.u.B.l[n][cc];
                    Bfl[nt][1] = *(const uint32_t*)&sm.u.B.l[n][cc + 8];
                }
                #pragma unroll
                for (int mt = 0; mt < 4; mt++)
                    #pragma unroll
                    for (int nt = 0; nt < 4; nt++) {
                        MMA(acc[h][mt][nt], Afh[mt], Bfh[nt]);
                        MMA(acc[h][mt][nt], Afh[mt], Bfl[nt]);
                        MMA(acc[h][mt][nt], Afl[mt], Bfh[nt]);
                    }
            }
        }
    }
    __syncthreads();
    // ---- epilogue: divide by l, write O
    #pragma unroll
    for (int mt = 0; mt < 4; mt++) {
        float il0 = 1.0f / sm.lrow[wm + mt * 16 + gr];
        float il1 = 1.0f / sm.lrow[wm + mt * 16 + gr + 8];
        #pragma unroll
        for (int h = 0; h < 2; h++)
            #pragma unroll
            for (int nt = 0; nt < 4; nt++) {
                int e = h * 128 + wn + nt * 8 + 2 * t4;
                int r0 = q0 + wm + mt * 16 + gr;
                float* O = out + ((size_t)bh * LSEQ + r0) * DIM + e;
                *(float2*)O = make_float2(acc[h][mt][nt][0] * il0,
                                          acc[h][mt][nt][1] * il0);
                *(float2*)(O + 8 * DIM) = make_float2(acc[h][mt][nt][2] * il1,
                                                      acc[h][mt][nt][3] * il1);
            }
    }
}

// ---------------------------------------------------------------- equivariant
__global__ void k_equiv(const float* __restrict__ xi, float* __restrict__ out) {
    __shared__ float xs[LSEQ][3];
    int bh = blockIdx.y;
    int tid = threadIdx.x;
    const float inv23 = 0.0021544346900318843f;

    for (int l = tid; l < LSEQ; l += 128) {
        float fl = (float)l;
        const float* xr = xi + ((size_t)bh * LSEQ + l) * 3;
        xs[l][0] = xr[0] + sinf(fl);
        xs[l][1] = xr[1] + cosf(fl);
        xs[l][2] = xr[2] + sinf(fl * inv23);
    }
    __syncthreads();

    int q = blockIdx.x * 128 + tid;
    float qx = xs[q][0], qy = xs[q][1], qz = xs[q][2];
    float m = -1e30f, denom = 0.0f, wn = 0.0f;
    float n0 = 0.0f, n1 = 0.0f, n2 = 0.0f;
    for (int k = 0; k <= q; k++) {
        float dx = qx - xs[k][0], dy = qy - xs[k][1], dz = qz - xs[k][2];
        float sq = dx * dx + dy * dy + dz * dz;
        if (sq > m) {
            float sc = expf(m - sq);
            denom *= sc; wn *= sc; n0 *= sc; n1 *= sc; n2 *= sc;
            m = sq;
        }
        float e = expf(sq - m);
        denom += e;
        if (k != q) { wn += e; n0 += e * xs[k][0]; n1 += e * xs[k][1]; n2 += e * xs[k][2]; }
    }
    float invd = 1.0f / denom;
    float bw = 0.5f * wn * invd;
    float* o = out + X_OFF + ((size_t)bh * LSEQ + q) * 3;
    o[0] = qx + 0.5f * n0 * invd - bw * qx;
    o[1] = qy + 0.5f * n1 * invd - bw * qy;
    o[2] = qz + 0.5f * n2 * invd - bw * qz;
}

// ---------------------------------------------------------------- edge
__global__ void k_edge(const float* __restrict__ edge, float* __restrict__ out) {
    int idx = blockIdx.x * 256 + threadIdx.x;
    int c = idx % EDGE_C;
    int l = (idx / EDGE_C) & (LSEQ - 1);
    float expo = (float)(c & ~1) * (1.0f / (float)EDGE_C);
    float ang = (float)l / powf(KAPPA, expo);
    float pe = (c & 1) ? cosf(ang) : sinf(ang);
    out[E_OFF + idx] = edge[idx] + pe;
}

// ----------------------------------------------------------------------------
extern "C" void kernel_launch(void* const* d_in, const int* in_sizes, int n_in,
                              void* d_out, int out_size) {
    const float* theta = (const float*)d_in[0];
    const float* xi    = (const float*)d_in[1];
    const float* edge  = (const float*)d_in[2];
    const float* Wq    = (const float*)d_in[3];
    const float* Wk    = (const float*)d_in[4];
    const float* Wv    = (const float*)d_in[5];
    float* out = (float*)d_out;

    static bool attr_done = false;
    if (!attr_done) {
        cudaFuncSetAttribute(k_qkv_mma,    cudaFuncAttributeMaxDynamicSharedMemorySize, (int)SMEM_DYN);
        cudaFuncSetAttribute(k_scores_mma, cudaFuncAttributeMaxDynamicSharedMemorySize, (int)SMEM_DYN);
        cudaFuncSetAttribute(k_sv,         cudaFuncAttributeMaxDynamicSharedMemorySize, (int)SV_SMEM);
        attr_done = true;
    }

    k_prep_w<<<(3 * DIM * DIM) / 256, 256>>>(Wq, Wk, Wv);
    k_theta_pe<<<H_ELEMS / 256, 256>>>(theta);
    k_qkv_mma<<<dim3(2, 256, 3), 256, SMEM_DYN>>>();
    k_vt<<<dim3(32, 8, 32), dim3(32, 8)>>>();
    k_scores_mma<<<dim3(8, 8, BH), 256, SMEM_DYN>>>();
    k_sv<<<dim3(8, BH), 256, SV_SMEM>>>(out);
    k_equiv<<<dim3(8, BH), 128>>>(xi, out);
    k_edge<<<E_ELEMS / 256, 256>>>(edge, out);
}

// round 6
// speedup vs baseline: 1.0356x; 1.0356x over previous
#include <cuda_runtime.h>
#include <cuda_bf16.h>
#include <math.h>
#include <stdint.h>

typedef __nv_bfloat16 bf16;

// ---------------------------------------------------------------- constants
#define LSEQ 1024
#define DIM  256
#define BH   32          // B*N heads
#define EDGE_C 112
#define KAPPA 10000.0f

#define H_ELEMS  (BH * LSEQ * DIM)
#define X_ELEMS  (BH * LSEQ * 3)
#define E_ELEMS  (4 * LSEQ * EDGE_C)
#define X_OFF    H_ELEMS
#define E_OFF    (H_ELEMS + X_ELEMS)

// ---------------------------------------------------------------- scratch
__device__ __align__(16) bf16 g_TPh[H_ELEMS], g_TPl[H_ELEMS];
__device__ __align__(16) bf16 g_Wh[3 * DIM * DIM], g_Wl[3 * DIM * DIM];
__device__ __align__(16) bf16 g_Qh[H_ELEMS], g_Ql[H_ELEMS];
__device__ __align__(16) bf16 g_Kh[H_ELEMS], g_Kl[H_ELEMS];
__device__ __align__(16) bf16 g_Vh[H_ELEMS], g_Vl[H_ELEMS];
__device__ __align__(16) bf16 g_VTh[H_ELEMS], g_VTl[H_ELEMS];      // [bh][e][s]
__device__ __align__(16) float g_S[(size_t)BH * LSEQ * LSEQ];

__device__ __forceinline__ void split2(float v, bf16& h, bf16& l) {
    h = __float2bfloat16(v);
    l = __float2bfloat16(v - __bfloat162float(h));
}

// ---------------------------------------------------------------- MMA core
#define MMA(acc, af, bf)                                                        \
    asm volatile(                                                               \
        "mma.sync.aligned.m16n8k16.row.col.f32.bf16.bf16.f32 "                  \
        "{%0,%1,%2,%3}, {%4,%5,%6,%7}, {%8,%9}, {%0,%1,%2,%3};"                 \
        : "+f"((acc)[0]), "+f"((acc)[1]), "+f"((acc)[2]), "+f"((acc)[3])        \
        : "r"((af)[0]), "r"((af)[1]), "r"((af)[2]), "r"((af)[3]),               \
          "r"((bf)[0]), "r"((bf)[1]))

#define KPAD 40   // 32 k + 8 pad: 80B row stride (16B aligned for cp.async)

struct Stage {
    bf16 Ah[128][KPAD], Al[128][KPAD], Bh[128][KPAD], Bl[128][KPAD];
};
#define SMEM_DYN (2 * sizeof(Stage))   // 81920 B

__device__ __forceinline__ void cp16(void* dst, const void* src) {
    uint32_t d = (uint32_t)__cvta_generic_to_shared(dst);
    asm volatile("cp.async.cg.shared.global [%0], [%1], 16;" :: "r"(d), "l"(src));
}
#define CP_COMMIT() asm volatile("cp.async.commit_group;" ::: "memory")
#define CP_WAIT1()  asm volatile("cp.async.wait_group 1;" ::: "memory")
#define CP_WAIT0()  asm volatile("cp.async.wait_group 0;" ::: "memory")

// Async-stage one 128x32 bf16 slice (256 threads, 2 x 16B each).
#define LDTA(SM, GP, LD) do {                                                   \
    int _r = tid >> 2, _c = (tid & 3) * 8;                                      \
    cp16(&SM[_r][_c],      (GP) + (size_t)_r * (LD) + _c);                      \
    cp16(&SM[_r + 64][_c], (GP) + (size_t)(_r + 64) * (LD) + _c);               \
} while (0)

#define LDSTAGE(ST, K0) do {                                                    \
    LDTA((ST).Ah, Agh + (K0), lda);                                             \
    LDTA((ST).Al, Agl + (K0), lda);                                             \
    LDTA((ST).Bh, Bgh + (K0), ldb);                                             \
    LDTA((ST).Bl, Bgl + (K0), ldb);                                             \
    CP_COMMIT();                                                                \
} while (0)

// Block tile 128x128, 8 warps (2m x 4n), warp tile 64x32, K-step 32,
// cp.async double-buffered.  3-pass hi/lo split.
__device__ __forceinline__ void gemm_main(
    Stage* stg,
    const bf16* __restrict__ Agh, const bf16* __restrict__ Agl, int lda,
    const bf16* __restrict__ Bgh, const bf16* __restrict__ Bgl, int ldb,
    int K, float acc[4][4][4], int tid)
{
    int wid = tid >> 5, lane = tid & 31;
    int wm = (wid >> 2) * 64, wn = (wid & 3) * 32;
    int gr = lane >> 2, t4 = lane & 3;
    int nst = K >> 5;

    LDSTAGE(stg[0], 0);

    for (int c = 0; c < nst; c++) {
        if (c + 1 < nst) { LDSTAGE(stg[(c + 1) & 1], (c + 1) * 32); CP_WAIT1(); }
        else             { CP_WAIT0(); }
        __syncthreads();
        Stage& s = stg[c & 1];
        #pragma unroll
        for (int kk = 0; kk < 32; kk += 16) {
            uint32_t Afh[4][4], Afl[4][4], Bfh[4][2], Bfl[4][2];
            #pragma unroll
            for (int mt = 0; mt < 4; mt++) {
                int r = wm + mt * 16 + gr, cc = kk + 2 * t4;
                Afh[mt][0] = *(const uint32_t*)&s.Ah[r][cc];
                Afh[mt][1] = *(const uint32_t*)&s.Ah[r + 8][cc];
                Afh[mt][2] = *(const uint32_t*)&s.Ah[r][cc + 8];
                Afh[mt][3] = *(const uint32_t*)&s.Ah[r + 8][cc + 8];
                Afl[mt][0] = *(const uint32_t*)&s.Al[r][cc];
                Afl[mt][1] = *(const uint32_t*)&s.Al[r + 8][cc];
                Afl[mt][2] = *(const uint32_t*)&s.Al[r][cc + 8];
                Afl[mt][3] = *(const uint32_t*)&s.Al[r + 8][cc + 8];
            }
            #pragma unroll
            for (int nt = 0; nt < 4; nt++) {
                int n = wn + nt * 8 + gr, cc = kk + 2 * t4;
                Bfh[nt][0] = *(const uint32_t*)&s.Bh[n][cc];
                Bfh[nt][1] = *(const uint32_t*)&s.Bh[n][cc + 8];
                Bfl[nt][0] = *(const uint32_t*)&s.Bl[n][cc];
                Bfl[nt][1] = *(const uint32_t*)&s.Bl[n][cc + 8];
            }
            #pragma unroll
            for (int mt = 0; mt < 4; mt++)
                #pragma unroll
                for (int nt = 0; nt < 4; nt++) {
                    MMA(acc[mt][nt], Afh[mt], Bfh[nt]);
                    MMA(acc[mt][nt], Afh[mt], Bfl[nt]);
                    MMA(acc[mt][nt], Afl[mt], Bfh[nt]);
                }
        }
        __syncthreads();
    }
}

// ---------------------------------------------------------------- prep
__global__ void k_prep_w(const float* __restrict__ Wq, const float* __restrict__ Wk,
                         const float* __restrict__ Wv) {
    int idx = blockIdx.x * 256 + threadIdx.x;
    int mat = idx >> 16, off = idx & 65535;
    const float* W = (mat == 0) ? Wq : (mat == 1) ? Wk : Wv;
    split2(W[off], g_Wh[idx], g_Wl[idx]);
}

__global__ void k_theta_pe(const float* __restrict__ theta) {
    int idx = blockIdx.x * 256 + threadIdx.x;
    int i = idx & (DIM - 1);
    int l = (idx >> 8) & (LSEQ - 1);
    float expo = (float)(i & ~1) * (1.0f / (float)DIM);
    float ang = (float)l / powf(KAPPA, expo);
    float pe = (i & 1) ? cosf(ang) : sinf(ang);
    split2(theta[idx] + pe, g_TPh[idx], g_TPl[idx]);
}

// ---------------------------------------------------------------- QKV
__global__ void __launch_bounds__(256) k_qkv_mma() {
    extern __shared__ char smraw[];
    Stage* stg = reinterpret_cast<Stage*>(smraw);
    int tid = threadIdx.x;
    int e0 = blockIdx.x * 128, m0 = blockIdx.y * 128, mat = blockIdx.z;

    float acc[4][4][4] = {};
    gemm_main(stg, g_TPh + (size_t)m0 * DIM, g_TPl + (size_t)m0 * DIM, DIM,
              g_Wh + (size_t)mat * 65536 + (size_t)e0 * DIM,
              g_Wl + (size_t)mat * 65536 + (size_t)e0 * DIM, DIM,
              DIM, acc, tid);

    bf16 *oh, *ol;
    if (mat == 0)      { oh = g_Qh; ol = g_Ql; }
    else if (mat == 1) { oh = g_Kh; ol = g_Kl; }
    else               { oh = g_Vh; ol = g_Vl; }
    int wid = tid >> 5, lane = tid & 31;
    int wm = (wid >> 2) * 64, wn = (wid & 3) * 32;
    int gr = lane >> 2, t4 = lane & 3;
    #pragma unroll
    for (int mt = 0; mt < 4; mt++)
        #pragma unroll
        for (int nt = 0; nt < 4; nt++)
            #pragma unroll
            for (int half = 0; half < 2; half++) {
                int r = m0 + wm + mt * 16 + gr + half * 8;
                int c = e0 + wn + nt * 8 + 2 * t4;
                __nv_bfloat162 h2, l2;
                split2(acc[mt][nt][half * 2],     h2.x, l2.x);
                split2(acc[mt][nt][half * 2 + 1], h2.y, l2.y);
                *(uint32_t*)&oh[(size_t)r * DIM + c] = *(uint32_t*)&h2;
                *(uint32_t*)&ol[(size_t)r * DIM + c] = *(uint32_t*)&l2;
            }
}

// ---------------------------------------------------------------- V transpose
__global__ void k_vt() {
    __shared__ bf16 th[32][33], tl[32][33];
    int s0 = blockIdx.x * 32, e0 = blockIdx.y * 32, bh = blockIdx.z;
    int tx = threadIdx.x, ty = threadIdx.y;
    #pragma unroll
    for (int j = 0; j < 4; j++) {
        int sr = s0 + ty + j * 8;
        size_t src = ((size_t)bh * LSEQ + sr) * DIM + e0 + tx;
        th[ty + j * 8][tx] = g_Vh[src];
        tl[ty + j * 8][tx] = g_Vl[src];
    }
    __syncthreads();
    #pragma unroll
    for (int j = 0; j < 4; j++) {
        int e = e0 + ty + j * 8;
        size_t dst = ((size_t)bh * DIM + e) * LSEQ + s0 + tx;
        g_VTh[dst] = th[tx][ty + j * 8];
        g_VTl[dst] = tl[tx][ty + j * 8];
    }
}

// ---------------------------------------------------------------- scores
__global__ void __launch_bounds__(256) k_scores_mma() {
    int kt = blockIdx.x, qt = blockIdx.y, bh = blockIdx.z;
    if (kt > qt) return;
    extern __shared__ char smraw[];
    Stage* stg = reinterpret_cast<Stage*>(smraw);
    int tid = threadIdx.x;
    int q0 = qt * 128, c0 = kt * 128;
    size_t qb = ((size_t)bh * LSEQ + q0) * DIM;
    size_t kb = ((size_t)bh * LSEQ + c0) * DIM;

    float acc[4][4][4] = {};
    gemm_main(stg, g_Qh + qb, g_Ql + qb, DIM, g_Kh + kb, g_Kl + kb, DIM,
              DIM, acc, tid);

    int wid = tid >> 5, lane = tid & 31;
    int wm = (wid >> 2) * 64, wn = (wid & 3) * 32;
    int gr = lane >> 2, t4 = lane & 3;
    float* S = g_S + (size_t)bh * LSEQ * LSEQ;
    #pragma unroll
    for (int mt = 0; mt < 4; mt++)
        #pragma unroll
        for (int nt = 0; nt < 4; nt++)
            #pragma unroll
            for (int half = 0; half < 2; half++) {
                int r = q0 + wm + mt * 16 + gr + half * 8;
                int c = c0 + wn + nt * 8 + 2 * t4;
                float2 v = make_float2(acc[mt][nt][half * 2] * 0.0625f,
                                       acc[mt][nt][half * 2 + 1] * 0.0625f);
                *(float2*)&S[(size_t)r * LSEQ + c] = v;
            }
}

// ---------------------------------------------------------------- fused softmax+PV
// et-split: grid (2 et, 8 qt, 32 bh).  Per block: online softmax over kt
// tiles of S (recomputed in both e-halves; exp is cheap), P in smem only,
// O accumulated in regs (128q x 128e, acc = 64 regs/thread like old k_pv).
// V-tile cp.async overlaps the softmax compute.
struct SvSmem {
    float Ss[128][132];                 // S tile stage (fp32)
    bf16 Ph[128][136], Pl[128][136];    // P tile (hi/lo)
    bf16 Bh[128][136], Bl[128][136];    // VT tile stage (hi/lo)
    float mrow[128], lrow[128], frow[128];
};
#define SV_SMEM sizeof(SvSmem)

__global__ void __launch_bounds__(256) k_sv2(float* __restrict__ out) {
    extern __shared__ char smraw[];
    SvSmem& sm = *reinterpret_cast<SvSmem*>(smraw);
    int tid = threadIdx.x, wid = tid >> 5, lane = tid & 31;
    int et = blockIdx.x;
    int qt = 7 - blockIdx.y, bh = blockIdx.z;     // heavy blocks first
    int q0 = qt * 128, e0 = et * 128;
    int wm = (wid >> 2) * 64, wn = (wid & 3) * 32;
    int gr = lane >> 2, t4 = lane & 3;
    const float* Sbase = g_S + (size_t)bh * LSEQ * LSEQ + (size_t)q0 * LSEQ;
    const bf16* vthb = g_VTh + ((size_t)bh * DIM + e0) * LSEQ;
    const bf16* vtlb = g_VTl + ((size_t)bh * DIM + e0) * LSEQ;

    if (tid < 128) { sm.mrow[tid] = -1e30f; sm.lrow[tid] = 0.0f; }
    float acc[4][4][4] = {};
    int r2 = tid >> 1, half = tid & 1;            // softmax: 2 thr per row
    int cb = half * 64;

    for (int kt = 0; kt <= qt; kt++) {
        __syncthreads();                          // prev MMA done; stats init
        // ---- stage S tile (128x128 f32), then V tile (overlaps softmax)
        #pragma unroll
        for (int i = 0; i < 16; i++) {
            int u = i * 256 + tid, r = u >> 5, c = u & 31;
            cp16(&sm.Ss[r][c * 4], Sbase + (size_t)r * LSEQ + kt * 128 + c * 4);
        }
        CP_COMMIT();
        #pragma unroll
        for (int i = 0; i < 8; i++) {
            int u = i * 256 + tid, r = (u >> 4) & 127, c = u & 15;
            cp16(&sm.Bh[r][c * 8], vthb + (size_t)r * LSEQ + kt * 128 + c * 8);
            cp16(&sm.Bl[r][c * 8], vtlb + (size_t)r * LSEQ + kt * 128 + c * 8);
        }
        CP_COMMIT();
        CP_WAIT1();                               // S done, V may still fly
        __syncthreads();
        // ---- online softmax for 64 cols of one row
        bool diag = (kt == qt);
        float mloc = -1e30f;
        #pragma unroll
        for (int j = 0; j < 64; j++) {
            float s = sm.Ss[r2][cb + j];
            if (diag && (cb + j > r2)) s = -1e30f;
            mloc = fmaxf(mloc, s);
        }
        mloc = fmaxf(mloc, __shfl_xor_sync(0xFFFFFFFFu, mloc, 1));
        float mold = sm.mrow[r2];
        float mnew = fmaxf(mold, mloc);
        float fac = expf(mold - mnew);
        float ssum = 0.0f;
        #pragma unroll
        for (int j = 0; j < 64; j += 2) {
            float s0 = sm.Ss[r2][cb + j];
            float s1 = sm.Ss[r2][cb + j + 1];
            bool v0 = !diag || (cb + j     <= r2);
            bool v1 = !diag || (cb + j + 1 <= r2);
            float p0 = v0 ? expf(s0 - mnew) : 0.0f;
            float p1 = v1 ? expf(s1 - mnew) : 0.0f;
            ssum += p0 + p1;
            __nv_bfloat162 h2, l2;
            split2(p0, h2.x, l2.x); split2(p1, h2.y, l2.y);
            *(uint32_t*)&sm.Ph[r2][cb + j] = *(uint32_t*)&h2;
            *(uint32_t*)&sm.Pl[r2][cb + j] = *(uint32_t*)&l2;
        }
        ssum += __shfl_xor_sync(0xFFFFFFFFu, ssum, 1);
        if (!half) {
            sm.mrow[r2] = mnew;
            sm.lrow[r2] = sm.lrow[r2] * fac + ssum;
            sm.frow[r2] = fac;
        }
        __syncthreads();                          // P, frow valid
        // ---- rescale O accumulator
        #pragma unroll
        for (int mt = 0; mt < 4; mt++) {
            float f0 = sm.frow[wm + mt * 16 + gr];
            float f1 = sm.frow[wm + mt * 16 + gr + 8];
            #pragma unroll
            for (int nt = 0; nt < 4; nt++) {
                acc[mt][nt][0] *= f0; acc[mt][nt][1] *= f0;
                acc[mt][nt][2] *= f1; acc[mt][nt][3] *= f1;
            }
        }
        CP_WAIT0();                               // V tile done
        __syncthreads();
        // ---- PV MMA over 128 k
        #pragma unroll
        for (int kk = 0; kk < 128; kk += 16) {
            uint32_t Afh[4][4], Afl[4][4], Bfh[4][2], Bfl[4][2];
            #pragma unroll
            for (int mt = 0; mt < 4; mt++) {
                int r = wm + mt * 16 + gr, cc = kk + 2 * t4;
                Afh[mt][0] = *(const uint32_t*)&sm.Ph[r][cc];
                Afh[mt][1] = *(const uint32_t*)&sm.Ph[r + 8][cc];
                Afh[mt][2] = *(const uint32_t*)&sm.Ph[r][cc + 8];
                Afh[mt][3] = *(const uint32_t*)&sm.Ph[r + 8][cc + 8];
                Afl[mt][0] = *(const uint32_t*)&sm.Pl[r][cc];
                Afl[mt][1] = *(const uint32_t*)&sm.Pl[r + 8][cc];
                Afl[mt][2] = *(const uint32_t*)&sm.Pl[r][cc + 8];
                Afl[mt][3] = *(const uint32_t*)&sm.Pl[r + 8][cc + 8];
            }
            #pragma unroll
            for (int nt = 0; nt < 4; nt++) {
                int n = wn + nt * 8 + gr, cc = kk + 2 * t4;
                Bfh[nt][0] = *(const uint32_t*)&sm.Bh[n][cc];
                Bfh[nt][1] = *(const uint32_t*)&sm.Bh[n][cc + 8];
                Bfl[nt][0] = *(const uint32_t*)&sm.Bl[n][cc];
                Bfl[nt][1] = *(const uint32_t*)&sm.Bl[n][cc + 8];
            }
            #pragma unroll
            for (int mt = 0; mt < 4; mt++)
                #pragma unroll
                for (int nt = 0; nt < 4; nt++) {
                    MMA(acc[mt][nt], Afh[mt], Bfh[nt]);
                    MMA(acc[mt][nt], Afh[mt], Bfl[nt]);
                    MMA(acc[mt][nt], Afl[mt], Bfh[nt]);
                }
        }
    }
    __syncthreads();
    // ---- epilogue: divide by l, write O
    #pragma unroll
    for (int mt = 0; mt < 4; mt++) {
        float il0 = 1.0f / sm.lrow[wm + mt * 16 + gr];
        float il1 = 1.0f / sm.lrow[wm + mt * 16 + gr + 8];
        #pragma unroll
        for (int nt = 0; nt < 4; nt++) {
            int e = e0 + wn + nt * 8 + 2 * t4;
            int r0 = q0 + wm + mt * 16 + gr;
            float* O = out + ((size_t)bh * LSEQ + r0) * DIM + e;
            *(float2*)O = make_float2(acc[mt][nt][0] * il0,
                                      acc[mt][nt][1] * il0);
            *(float2*)(O + 8 * DIM) = make_float2(acc[mt][nt][2] * il1,
                                                  acc[mt][nt][3] * il1);
        }
    }
}

// ---------------------------------------------------------------- equivariant
__global__ void k_equiv(const float* __restrict__ xi, float* __restrict__ out) {
    __shared__ float xs[LSEQ][3];
    int bh = blockIdx.y;
    int tid = threadIdx.x;
    const float inv23 = 0.0021544346900318843f;

    for (int l = tid; l < LSEQ; l += 128) {
        float fl = (float)l;
        const float* xr = xi + ((size_t)bh * LSEQ + l) * 3;
        xs[l][0] = xr[0] + sinf(fl);
        xs[l][1] = xr[1] + cosf(fl);
        xs[l][2] = xr[2] + sinf(fl * inv23);
    }
    __syncthreads();

    int q = blockIdx.x * 128 + tid;
    float qx = xs[q][0], qy = xs[q][1], qz = xs[q][2];
    float m = -1e30f, denom = 0.0f, wn = 0.0f;
    float n0 = 0.0f, n1 = 0.0f, n2 = 0.0f;
    for (int k = 0; k <= q; k++) {
        float dx = qx - xs[k][0], dy = qy - xs[k][1], dz = qz - xs[k][2];
        float sq = dx * dx + dy * dy + dz * dz;
        if (sq > m) {
            float sc = expf(m - sq);
            denom *= sc; wn *= sc; n0 *= sc; n1 *= sc; n2 *= sc;
            m = sq;
        }
        float e = expf(sq - m);
        denom += e;
        if (k != q) { wn += e; n0 += e * xs[k][0]; n1 += e * xs[k][1]; n2 += e * xs[k][2]; }
    }
    float invd = 1.0f / denom;
    float bw = 0.5f * wn * invd;
    float* o = out + X_OFF + ((size_t)bh * LSEQ + q) * 3;
    o[0] = qx + 0.5f * n0 * invd - bw * qx;
    o[1] = qy + 0.5f * n1 * invd - bw * qy;
    o[2] = qz + 0.5f * n2 * invd - bw * qz;
}

// ---------------------------------------------------------------- edge
__global__ void k_edge(const float* __restrict__ edge, float* __restrict__ out) {
    int idx = blockIdx.x * 256 + threadIdx.x;
    int c = idx % EDGE_C;
    int l = (idx / EDGE_C) & (LSEQ - 1);
    float expo = (float)(c & ~1) * (1.0f / (float)EDGE_C);
    float ang = (float)l / powf(KAPPA, expo);
    float pe = (c & 1) ? cosf(ang) : sinf(ang);
    out[E_OFF + idx] = edge[idx] + pe;
}

// ----------------------------------------------------------------------------
extern "C" void kernel_launch(void* const* d_in, const int* in_sizes, int n_in,
                              void* d_out, int out_size) {
    const float* theta = (const float*)d_in[0];
    const float* xi    = (const float*)d_in[1];
    const float* edge  = (const float*)d_in[2];
    const float* Wq    = (const float*)d_in[3];
    const float* Wk    = (const float*)d_in[4];
    const float* Wv    = (const float*)d_in[5];
    float* out = (float*)d_out;

    static bool attr_done = false;
    if (!attr_done) {
        cudaFuncSetAttribute(k_qkv_mma,    cudaFuncAttributeMaxDynamicSharedMemorySize, (int)SMEM_DYN);
        cudaFuncSetAttribute(k_scores_mma, cudaFuncAttributeMaxDynamicSharedMemorySize, (int)SMEM_DYN);
        cudaFuncSetAttribute(k_sv2,        cudaFuncAttributeMaxDynamicSharedMemorySize, (int)SV_SMEM);
        attr_done = true;
    }

    k_prep_w<<<(3 * DIM * DIM) / 256, 256>>>(Wq, Wk, Wv);
    k_theta_pe<<<H_ELEMS / 256, 256>>>(theta);
    k_qkv_mma<<<dim3(2, 256, 3), 256, SMEM_DYN>>>();
    k_vt<<<dim3(32, 8, 32), dim3(32, 8)>>>();
    k_scores_mma<<<dim3(8, 8, BH), 256, SMEM_DYN>>>();
    k_sv2<<<dim3(2, 8, BH), 256, SV_SMEM>>>(out);
    k_equiv<<<dim3(8, BH), 128>>>(xi, out);
    k_edge<<<E_ELEMS / 256, 256>>>(edge, out);
}

// round 7
// speedup vs baseline: 1.0560x; 1.0197x over previous
#include <cuda_runtime.h>
#include <cuda_bf16.h>
#include <math.h>
#include <stdint.h>

typedef __nv_bfloat16 bf16;

// ---------------------------------------------------------------- constants
#define LSEQ 1024
#define DIM  256
#define BH   32          // B*N heads
#define EDGE_C 112
#define KAPPA 10000.0f

#define H_ELEMS  (BH * LSEQ * DIM)
#define X_ELEMS  (BH * LSEQ * 3)
#define E_ELEMS  (4 * LSEQ * EDGE_C)
#define X_OFF    H_ELEMS
#define E_OFF    (H_ELEMS + X_ELEMS)

// ---------------------------------------------------------------- scratch
__device__ __align__(16) bf16 g_TPh[H_ELEMS], g_TPl[H_ELEMS];
__device__ __align__(16) bf16 g_Wh[3 * DIM * DIM], g_Wl[3 * DIM * DIM];
__device__ __align__(16) bf16 g_Qh[H_ELEMS], g_Ql[H_ELEMS];
__device__ __align__(16) bf16 g_Kh[H_ELEMS], g_Kl[H_ELEMS];
__device__ __align__(16) bf16 g_Vh[H_ELEMS], g_Vl[H_ELEMS];
__device__ __align__(16) bf16 g_VTh[H_ELEMS], g_VTl[H_ELEMS];      // [bh][e][s]
__device__ __align__(16) float g_S[(size_t)BH * LSEQ * LSEQ];
__device__ __align__(16) bf16 g_Ph[(size_t)BH * LSEQ * LSEQ];
__device__ __align__(16) bf16 g_Pl[(size_t)BH * LSEQ * LSEQ];

__device__ __forceinline__ void split2(float v, bf16& h, bf16& l) {
    h = __float2bfloat16(v);
    l = __float2bfloat16(v - __bfloat162float(h));
}

// ---------------------------------------------------------------- MMA core
#define MMA(acc, af, bf)                                                        \
    asm volatile(                                                               \
        "mma.sync.aligned.m16n8k16.row.col.f32.bf16.bf16.f32 "                  \
        "{%0,%1,%2,%3}, {%4,%5,%6,%7}, {%8,%9}, {%0,%1,%2,%3};"                 \
        : "+f"((acc)[0]), "+f"((acc)[1]), "+f"((acc)[2]), "+f"((acc)[3])        \
        : "r"((af)[0]), "r"((af)[1]), "r"((af)[2]), "r"((af)[3]),               \
          "r"((bf)[0]), "r"((bf)[1]))

#define LDM4(r0, r1, r2, r3, a)                                                 \
    asm volatile("ldmatrix.sync.aligned.m8n8.x4.shared.b16 {%0,%1,%2,%3}, [%4];"\
        : "=r"(r0), "=r"(r1), "=r"(r2), "=r"(r3) : "r"(a))

#define KPAD 40   // 32 k + 8 pad: 80B row stride; ldmatrix rows conflict-free

struct Stage {
    bf16 Ah[128][KPAD], Al[128][KPAD], Bh[128][KPAD], Bl[128][KPAD];
};
#define SMEM_DYN (2 * sizeof(Stage))   // 81920 B

__device__ __forceinline__ void cp16(void* dst, const void* src) {
    uint32_t d = (uint32_t)__cvta_generic_to_shared(dst);
    asm volatile("cp.async.cg.shared.global [%0], [%1], 16;" :: "r"(d), "l"(src));
}
#define CP_COMMIT() asm volatile("cp.async.commit_group;" ::: "memory")
#define CP_WAIT1()  asm volatile("cp.async.wait_group 1;" ::: "memory")
#define CP_WAIT0()  asm volatile("cp.async.wait_group 0;" ::: "memory")

// Async-stage one 128x32 bf16 slice (256 threads, 2 x 16B each).
#define LDTA(SM, GP, LD) do {                                                   \
    int _r = tid >> 2, _c = (tid & 3) * 8;                                      \
    cp16(&SM[_r][_c],      (GP) + (size_t)_r * (LD) + _c);                      \
    cp16(&SM[_r + 64][_c], (GP) + (size_t)(_r + 64) * (LD) + _c);               \
} while (0)

#define LDSTAGE(ST, K0) do {                                                    \
    LDTA((ST).Ah, Agh + (K0), lda);                                             \
    LDTA((ST).Al, Agl + (K0), lda);                                             \
    LDTA((ST).Bh, Bgh + (K0), ldb);                                             \
    LDTA((ST).Bl, Bgl + (K0), ldb);                                             \
    CP_COMMIT();                                                                \
} while (0)

// Block tile 128x128, 8 warps (2m x 4n), warp tile 64x32, K-step 32,
// cp.async double-buffered, ldmatrix fragment loads, 3-pass hi/lo split.
__device__ __forceinline__ void gemm_main(
    Stage* stg,
    const bf16* __restrict__ Agh, const bf16* __restrict__ Agl, int lda,
    const bf16* __restrict__ Bgh, const bf16* __restrict__ Bgl, int ldb,
    int K, float acc[4][4][4], int tid)
{
    int wid = tid >> 5, lane = tid & 31;
    int wm = (wid >> 2) * 64, wn = (wid & 3) * 32;
    int nst = K >> 5;

    // ldmatrix per-lane source coordinates (element units within a Stage array)
    int aRow = wm + (lane & 15);                  // + mt*16
    int aCol = (lane >> 4) * 8;                   // + kk
    int bRow = wn + (lane & 7) + ((lane >> 4) * 8);  // + ntp*16
    int bCol = ((lane >> 3) & 1) * 8;             // + kk

    LDSTAGE(stg[0], 0);

    for (int c = 0; c < nst; c++) {
        if (c + 1 < nst) { LDSTAGE(stg[(c + 1) & 1], (c + 1) * 32); CP_WAIT1(); }
        else             { CP_WAIT0(); }
        __syncthreads();
        Stage& s = stg[c & 1];
        uint32_t ah0 = (uint32_t)__cvta_generic_to_shared(&s.Ah[aRow][aCol]);
        uint32_t al0 = (uint32_t)__cvta_generic_to_shared(&s.Al[aRow][aCol]);
        uint32_t bh0 = (uint32_t)__cvta_generic_to_shared(&s.Bh[bRow][bCol]);
        uint32_t bl0 = (uint32_t)__cvta_generic_to_shared(&s.Bl[bRow][bCol]);
        #pragma unroll
        for (int kk = 0; kk < 32; kk += 16) {
            uint32_t Afh[4][4], Afl[4][4], Bfh[4][2], Bfl[4][2];
            #pragma unroll
            for (int mt = 0; mt < 4; mt++) {
                uint32_t ao = (uint32_t)(mt * 16 * KPAD + kk) * 2;
                LDM4(Afh[mt][0], Afh[mt][1], Afh[mt][2], Afh[mt][3], ah0 + ao);
                LDM4(Afl[mt][0], Afl[mt][1], Afl[mt][2], Afl[mt][3], al0 + ao);
            }
            #pragma unroll
            for (int ntp = 0; ntp < 2; ntp++) {
                uint32_t bo = (uint32_t)(ntp * 16 * KPAD + kk) * 2;
                LDM4(Bfh[2 * ntp][0], Bfh[2 * ntp][1],
                     Bfh[2 * ntp + 1][0], Bfh[2 * ntp + 1][1], bh0 + bo);
                LDM4(Bfl[2 * ntp][0], Bfl[2 * ntp][1],
                     Bfl[2 * ntp + 1][0], Bfl[2 * ntp + 1][1], bl0 + bo);
            }
            #pragma unroll
            for (int mt = 0; mt < 4; mt++)
                #pragma unroll
                for (int nt = 0; nt < 4; nt++) {
                    MMA(acc[mt][nt], Afh[mt], Bfh[nt]);
                    MMA(acc[mt][nt], Afh[mt], Bfl[nt]);
                    MMA(acc[mt][nt], Afl[mt], Bfh[nt]);
                }
        }
        __syncthreads();
    }
}

// ---------------------------------------------------------------- prep
__global__ void k_prep_w(const float* __restrict__ Wq, const float* __restrict__ Wk,
                         const float* __restrict__ Wv) {
    int idx = blockIdx.x * 256 + threadIdx.x;
    int mat = idx >> 16, off = idx & 65535;
    const float* W = (mat == 0) ? Wq : (mat == 1) ? Wk : Wv;
    split2(W[off], g_Wh[idx], g_Wl[idx]);
}

__global__ void k_theta_pe(const float* __restrict__ theta) {
    int idx = blockIdx.x * 256 + threadIdx.x;
    int i = idx & (DIM - 1);
    int l = (idx >> 8) & (LSEQ - 1);
    float expo = (float)(i & ~1) * (1.0f / (float)DIM);
    float ang = (float)l / powf(KAPPA, expo);
    float pe = (i & 1) ? cosf(ang) : sinf(ang);
    split2(theta[idx] + pe, g_TPh[idx], g_TPl[idx]);
}

// ---------------------------------------------------------------- QKV
__global__ void __launch_bounds__(256) k_qkv_mma() {
    extern __shared__ char smraw[];
    Stage* stg = reinterpret_cast<Stage*>(smraw);
    int tid = threadIdx.x;
    int e0 = blockIdx.x * 128, m0 = blockIdx.y * 128, mat = blockIdx.z;

    float acc[4][4][4] = {};
    gemm_main(stg, g_TPh + (size_t)m0 * DIM, g_TPl + (size_t)m0 * DIM, DIM,
              g_Wh + (size_t)mat * 65536 + (size_t)e0 * DIM,
              g_Wl + (size_t)mat * 65536 + (size_t)e0 * DIM, DIM,
              DIM, acc, tid);

    bf16 *oh, *ol;
    if (mat == 0)      { oh = g_Qh; ol = g_Ql; }
    else if (mat == 1) { oh = g_Kh; ol = g_Kl; }
    else               { oh = g_Vh; ol = g_Vl; }
    int wid = tid >> 5, lane = tid & 31;
    int wm = (wid >> 2) * 64, wn = (wid & 3) * 32;
    int gr = lane >> 2, t4 = lane & 3;
    #pragma unroll
    for (int mt = 0; mt < 4; mt++)
        #pragma unroll
        for (int nt = 0; nt < 4; nt++)
            #pragma unroll
            for (int half = 0; half < 2; half++) {
                int r = m0 + wm + mt * 16 + gr + half * 8;
                int c = e0 + wn + nt * 8 + 2 * t4;
                __nv_bfloat162 h2, l2;
                split2(acc[mt][nt][half * 2],     h2.x, l2.x);
                split2(acc[mt][nt][half * 2 + 1], h2.y, l2.y);
                *(uint32_t*)&oh[(size_t)r * DIM + c] = *(uint32_t*)&h2;
                *(uint32_t*)&ol[(size_t)r * DIM + c] = *(uint32_t*)&l2;
            }
}

// ---------------------------------------------------------------- V transpose
__global__ void k_vt() {
    __shared__ bf16 th[32][33], tl[32][33];
    int s0 = blockIdx.x * 32, e0 = blockIdx.y * 32, bh = blockIdx.z;
    int tx = threadIdx.x, ty = threadIdx.y;
    #pragma unroll
    for (int j = 0; j < 4; j++) {
        int sr = s0 + ty + j * 8;
        size_t src = ((size_t)bh * LSEQ + sr) * DIM + e0 + tx;
        th[ty + j * 8][tx] = g_Vh[src];
        tl[ty + j * 8][tx] = g_Vl[src];
    }
    __syncthreads();
    #pragma unroll
    for (int j = 0; j < 4; j++) {
        int e = e0 + ty + j * 8;
        size_t dst = ((size_t)bh * DIM + e) * LSEQ + s0 + tx;
        g_VTh[dst] = th[tx][ty + j * 8];
        g_VTl[dst] = tl[tx][ty + j * 8];
    }
}

// ---------------------------------------------------------------- scores
__global__ void __launch_bounds__(256) k_scores_mma() {
    int kt = blockIdx.x, qt = blockIdx.y, bh = blockIdx.z;
    if (kt > qt) return;
    extern __shared__ char smraw[];
    Stage* stg = reinterpret_cast<Stage*>(smraw);
    int tid = threadIdx.x;
    int q0 = qt * 128, c0 = kt * 128;
    size_t qb = ((size_t)bh * LSEQ + q0) * DIM;
    size_t kb = ((size_t)bh * LSEQ + c0) * DIM;

    float acc[4][4][4] = {};
    gemm_main(stg, g_Qh + qb, g_Ql + qb, DIM, g_Kh + kb, g_Kl + kb, DIM,
              DIM, acc, tid);

    int wid = tid >> 5, lane = tid & 31;
    int wm = (wid >> 2) * 64, wn = (wid & 3) * 32;
    int gr = lane >> 2, t4 = lane & 3;
    float* S = g_S + (size_t)bh * LSEQ * LSEQ;
    #pragma unroll
    for (int mt = 0; mt < 4; mt++)
        #pragma unroll
        for (int nt = 0; nt < 4; nt++)
            #pragma unroll
            for (int half = 0; half < 2; half++) {
                int r = q0 + wm + mt * 16 + gr + half * 8;
                int c = c0 + wn + nt * 8 + 2 * t4;
                float2 v = make_float2(acc[mt][nt][half * 2] * 0.0625f,
                                       acc[mt][nt][half * 2 + 1] * 0.0625f);
                *(float2*)&S[(size_t)r * LSEQ + c] = v;
            }
}

// ---------------------------------------------------------------- softmax
__global__ void k_softmax() {
    int warp = threadIdx.x >> 5, lane = threadIdx.x & 31;
    int row = blockIdx.x * 8 + warp;
    int bh = row >> 10, q = row & (LSEQ - 1);
    size_t base = (size_t)bh * LSEQ * LSEQ + (size_t)q * LSEQ;
    const float* Srow = g_S + base;
    int len = q + 1;

    float m = -1e30f;
    for (int k = lane; k < len; k += 32) m = fmaxf(m, Srow[k]);
    #pragma unroll
    for (int o = 16; o; o >>= 1) m = fmaxf(m, __shfl_xor_sync(0xFFFFFFFFu, m, o));
    float ssum = 0.0f;
    for (int k = lane; k < len; k += 32) ssum += expf(Srow[k] - m);
    #pragma unroll
    for (int o = 16; o; o >>= 1) ssum += __shfl_xor_sync(0xFFFFFFFFu, ssum, o);
    float inv = 1.0f / ssum;
    for (int k = lane; k < len; k += 32) {
        float p = expf(Srow[k] - m) * inv;
        bf16 h, l; split2(p, h, l);
        g_Ph[base + k] = h; g_Pl[base + k] = l;
    }
    int end = ((q >> 7) + 1) << 7;
    for (int k = q + 1 + lane; k < end; k += 32) {
        g_Ph[base + k] = __float2bfloat16(0.0f);
        g_Pl[base + k] = __float2bfloat16(0.0f);
    }
}

// ---------------------------------------------------------------- PV
__global__ void __launch_bounds__(256) k_pv_mma(float* __restrict__ out) {
    int et = blockIdx.x, qt = blockIdx.y, bh = blockIdx.z;
    extern __shared__ char smraw[];
    Stage* stg = reinterpret_cast<Stage*>(smraw);
    int tid = threadIdx.x;
    int q0 = qt * 128, e0 = et * 128;
    size_t pb = (size_t)bh * LSEQ * LSEQ + (size_t)q0 * LSEQ;
    size_t vb = ((size_t)bh * DIM + e0) * LSEQ;

    float acc[4][4][4] = {};
    gemm_main(stg, g_Ph + pb, g_Pl + pb, LSEQ, g_VTh + vb, g_VTl + vb, LSEQ,
              (qt + 1) * 128, acc, tid);

    int wid = tid >> 5, lane = tid & 31;
    int wm = (wid >> 2) * 64, wn = (wid & 3) * 32;
    int gr = lane >> 2, t4 = lane & 3;
    float* O = out + ((size_t)bh * LSEQ + q0) * DIM + e0;
    #pragma unroll
    for (int mt = 0; mt < 4; mt++)
        #pragma unroll
        for (int nt = 0; nt < 4; nt++)
            #pragma unroll
            for (int half = 0; half < 2; half++) {
                int r = wm + mt * 16 + gr + half * 8;
                int c = wn + nt * 8 + 2 * t4;
                float2 v = make_float2(acc[mt][nt][half * 2],
                                       acc[mt][nt][half * 2 + 1]);
                *(float2*)&O[(size_t)r * DIM + c] = v;
            }
}

// ---------------------------------------------------------------- equivariant
__global__ void k_equiv(const float* __restrict__ xi, float* __restrict__ out) {
    __shared__ float xs[LSEQ][3];
    int bh = blockIdx.y;
    int tid = threadIdx.x;
    const float inv23 = 0.0021544346900318843f;

    for (int l = tid; l < LSEQ; l += 128) {
        float fl = (float)l;
        const float* xr = xi + ((size_t)bh * LSEQ + l) * 3;
        xs[l][0] = xr[0] + sinf(fl);
        xs[l][1] = xr[1] + cosf(fl);
        xs[l][2] = xr[2] + sinf(fl * inv23);
    }
    __syncthreads();

    int q = blockIdx.x * 128 + tid;
    float qx = xs[q][0], qy = xs[q][1], qz = xs[q][2];
    float m = -1e30f, denom = 0.0f, wn = 0.0f;
    float n0 = 0.0f, n1 = 0.0f, n2 = 0.0f;
    for (int k = 0; k <= q; k++) {
        float dx = qx - xs[k][0], dy = qy - xs[k][1], dz = qz - xs[k][2];
        float sq = dx * dx + dy * dy + dz * dz;
        if (sq > m) {
            float sc = expf(m - sq);
            denom *= sc; wn *= sc; n0 *= sc; n1 *= sc; n2 *= sc;
            m = sq;
        }
        float e = expf(sq - m);
        denom += e;
        if (k != q) { wn += e; n0 += e * xs[k][0]; n1 += e * xs[k][1]; n2 += e * xs[k][2]; }
    }
    float invd = 1.0f / denom;
    float bw = 0.5f * wn * invd;
    float* o = out + X_OFF + ((size_t)bh * LSEQ + q) * 3;
    o[0] = qx + 0.5f * n0 * invd - bw * qx;
    o[1] = qy + 0.5f * n1 * invd - bw * qy;
    o[2] = qz + 0.5f * n2 * invd - bw * qz;
}

// ---------------------------------------------------------------- edge
__global__ void k_edge(const float* __restrict__ edge, float* __restrict__ out) {
    int idx = blockIdx.x * 256 + threadIdx.x;
    int c = idx % EDGE_C;
    int l = (idx / EDGE_C) & (LSEQ - 1);
    float expo = (float)(c & ~1) * (1.0f / (float)EDGE_C);
    float ang = (float)l / powf(KAPPA, expo);
    float pe = (c & 1) ? cosf(ang) : sinf(ang);
    out[E_OFF + idx] = edge[idx] + pe;
}

// ----------------------------------------------------------------------------
extern "C" void kernel_launch(void* const* d_in, const int* in_sizes, int n_in,
                              void* d_out, int out_size) {
    const float* theta = (const float*)d_in[0];
    const float* xi    = (const float*)d_in[1];
    const float* edge  = (const float*)d_in[2];
    const float* Wq    = (const float*)d_in[3];
    const float* Wk    = (const float*)d_in[4];
    const float* Wv    = (const float*)d_in[5];
    float* out = (float*)d_out;

    static bool attr_done = false;
    if (!attr_done) {
        cudaFuncSetAttribute(k_qkv_mma,    cudaFuncAttributeMaxDynamicSharedMemorySize, (int)SMEM_DYN);
        cudaFuncSetAttribute(k_scores_mma, cudaFuncAttributeMaxDynamicSharedMemorySize, (int)SMEM_DYN);
        cudaFuncSetAttribute(k_pv_mma,     cudaFuncAttributeMaxDynamicSharedMemorySize, (int)SMEM_DYN);
        attr_done = true;
    }

    k_prep_w<<<(3 * DIM * DIM) / 256, 256>>>(Wq, Wk, Wv);
    k_theta_pe<<<H_ELEMS / 256, 256>>>(theta);
    k_qkv_mma<<<dim3(2, 256, 3), 256, SMEM_DYN>>>();
    k_vt<<<dim3(32, 8, 32), dim3(32, 8)>>>();
    k_scores_mma<<<dim3(8, 8, BH), 256, SMEM_DYN>>>();
    k_softmax<<<(BH * LSEQ) / 8, 256>>>();
    k_pv_mma<<<dim3(2, 8, BH), 256, SMEM_DYN>>>(out);
    k_equiv<<<dim3(8, BH), 128>>>(xi, out);
    k_edge<<<E_ELEMS / 256, 256>>>(edge, out);
}

// round 9
// speedup vs baseline: 1.1924x; 1.1292x over previous
#include <cuda_runtime.h>
#include <cuda_bf16.h>
#include <cuda_fp16.h>
#include <math.h>
#include <stdint.h>

typedef __nv_bfloat16 bf16;

// ---------------------------------------------------------------- constants
#define LSEQ 1024
#define DIM  256
#define BH   32          // B*N heads
#define EDGE_C 112
#define KAPPA 10000.0f

#define H_ELEMS  (BH * LSEQ * DIM)
#define X_ELEMS  (BH * LSEQ * 3)
#define E_ELEMS  (4 * LSEQ * EDGE_C)
#define X_OFF    H_ELEMS
#define E_OFF    (H_ELEMS + X_ELEMS)

// ---------------------------------------------------------------- scratch
__device__ __align__(16) bf16 g_TPh[H_ELEMS], g_TPl[H_ELEMS];
__device__ __align__(16) bf16 g_Wh[3 * DIM * DIM], g_Wl[3 * DIM * DIM];
__device__ __align__(16) bf16 g_Qh[H_ELEMS], g_Ql[H_ELEMS];
__device__ __align__(16) bf16 g_Kh[H_ELEMS], g_Kl[H_ELEMS];
__device__ __align__(16) __half g_V16[H_ELEMS];                    // V (fp16)
__device__ __align__(16) __half g_VT16[H_ELEMS];                   // [bh][e][s]
__device__ __align__(16) float g_S[(size_t)BH * LSEQ * LSEQ];
__device__ __align__(16) __half g_Ph16[(size_t)BH * LSEQ * LSEQ];
__device__ __align__(16) __half g_Pl16[(size_t)BH * LSEQ * LSEQ];

__device__ __forceinline__ void split2(float v, bf16& h, bf16& l) {
    h = __float2bfloat16(v);
    l = __float2bfloat16(v - __bfloat162float(h));
}

// ---------------------------------------------------------------- MMA cores
#define MMA(acc, af, bf)                                                        \
    asm volatile(                                                               \
        "mma.sync.aligned.m16n8k16.row.col.f32.bf16.bf16.f32 "                  \
        "{%0,%1,%2,%3}, {%4,%5,%6,%7}, {%8,%9}, {%0,%1,%2,%3};"                 \
        : "+f"((acc)[0]), "+f"((acc)[1]), "+f"((acc)[2]), "+f"((acc)[3])        \
        : "r"((af)[0]), "r"((af)[1]), "r"((af)[2]), "r"((af)[3]),               \
          "r"((bf)[0]), "r"((bf)[1]))

#define MMAH(acc, af, bf)                                                       \
    asm volatile(                                                               \
        "mma.sync.aligned.m16n8k16.row.col.f32.f16.f16.f32 "                    \
        "{%0,%1,%2,%3}, {%4,%5,%6,%7}, {%8,%9}, {%0,%1,%2,%3};"                 \
        : "+f"((acc)[0]), "+f"((acc)[1]), "+f"((acc)[2]), "+f"((acc)[3])        \
        : "r"((af)[0]), "r"((af)[1]), "r"((af)[2]), "r"((af)[3]),               \
          "r"((bf)[0]), "r"((bf)1 ? (bf)[1] : (bf)[1]))

#undef MMAH
#define MMAH(acc, af, bf)                                                       \
    asm volatile(                                                               \
        "mma.sync.aligned.m16n8k16.row.col.f32.f16.f16.f32 "                    \
        "{%0,%1,%2,%3}, {%4,%5,%6,%7}, {%8,%9}, {%0,%1,%2,%3};"                 \
        : "+f"((acc)[0]), "+f"((acc)[1]), "+f"((acc)[2]), "+f"((acc)[3])        \
        : "r"((af)[0]), "r"((af)[1]), "r"((af)[2]), "r"((af)[3]),               \
          "r"((bf)[0]), "r"((bf)[1]))

#define KPAD 40   // 32 k + 8 pad: 80B row stride (16B aligned for cp.async)

struct Stage {
    bf16 Ah[128][KPAD], Al[128][KPAD], Bh[128][KPAD], Bl[128][KPAD];
};
#define SMEM_DYN (2 * sizeof(Stage))   // 81920 B

struct StageP {
    __half Ah[128][KPAD], Al[128][KPAD], Bh[128][KPAD];
};
#define SMEM_PV (2 * sizeof(StageP))   // 61440 B

__device__ __forceinline__ void cp16(void* dst, const void* src) {
    uint32_t d = (uint32_t)__cvta_generic_to_shared(dst);
    asm volatile("cp.async.cg.shared.global [%0], [%1], 16;" :: "r"(d), "l"(src));
}
#define CP_COMMIT() asm volatile("cp.async.commit_group;" ::: "memory")
#define CP_WAIT1()  asm volatile("cp.async.wait_group 1;" ::: "memory")
#define CP_WAIT0()  asm volatile("cp.async.wait_group 0;" ::: "memory")

// Async-stage one 128x32 16-bit slice (256 threads, 2 x 16B each).
#define LDTA(SM, GP, LD) do {                                                   \
    int _r = tid >> 2, _c = (tid & 3) * 8;                                      \
    cp16(&SM[_r][_c],      (GP) + (size_t)_r * (LD) + _c);                      \
    cp16(&SM[_r + 64][_c], (GP) + (size_t)(_r + 64) * (LD) + _c);               \
} while (0)

#define LDSTAGE(ST, K0) do {                                                    \
    LDTA((ST).Ah, Agh + (K0), lda);                                             \
    LDTA((ST).Al, Agl + (K0), lda);                                             \
    LDTA((ST).Bh, Bgh + (K0), ldb);                                             \
    LDTA((ST).Bl, Bgl + (K0), ldb);                                             \
    CP_COMMIT();                                                                \
} while (0)

// bf16 3-pass GEMM. diag=true: skip microtiles fully above the diagonal
// (valid only when block q0 == c0; skipped outputs stay 0).
__device__ __forceinline__ void gemm_main(
    Stage* stg,
    const bf16* __restrict__ Agh, const bf16* __restrict__ Agl, int lda,
    const bf16* __restrict__ Bgh, const bf16* __restrict__ Bgl, int ldb,
    int K, float acc[4][4][4], int tid, bool diag)
{
    int wid = tid >> 5, lane = tid & 31;
    int wm = (wid >> 2) * 64, wn = (wid & 3) * 32;
    int gr = lane >> 2, t4 = lane & 3;
    int nst = K >> 5;

    LDSTAGE(stg[0], 0);

    for (int c = 0; c < nst; c++) {
        if (c + 1 < nst) { LDSTAGE(stg[(c + 1) & 1], (c + 1) * 32); CP_WAIT1(); }
        else             { CP_WAIT0(); }
        __syncthreads();
        Stage& s = stg[c & 1];
        #pragma unroll
        for (int kk = 0; kk < 32; kk += 16) {
            uint32_t Afh[4][4], Afl[4][4], Bfh[4][2], Bfl[4][2];
            #pragma unroll
            for (int mt = 0; mt < 4; mt++) {
                int r = wm + mt * 16 + gr, cc = kk + 2 * t4;
                Afh[mt][0] = *(const uint32_t*)&s.Ah[r][cc];
                Afh[mt][1] = *(const uint32_t*)&s.Ah[r + 8][cc];
                Afh[mt][2] = *(const uint32_t*)&s.Ah[r][cc + 8];
                Afh[mt][3] = *(const uint32_t*)&s.Ah[r + 8][cc + 8];
                Afl[mt][0] = *(const uint32_t*)&s.Al[r][cc];
                Afl[mt][1] = *(const uint32_t*)&s.Al[r + 8][cc];
                Afl[mt][2] = *(const uint32_t*)&s.Al[r][cc + 8];
                Afl[mt][3] = *(const uint32_t*)&s.Al[r + 8][cc + 8];
            }
            #pragma unroll
            for (int nt = 0; nt < 4; nt++) {
                int n = wn + nt * 8 + gr, cc = kk + 2 * t4;
                Bfh[nt][0] = *(const uint32_t*)&s.Bh[n][cc];
                Bfh[nt][1] = *(const uint32_t*)&s.Bh[n][cc + 8];
                Bfl[nt][0] = *(const uint32_t*)&s.Bl[n][cc];
                Bfl[nt][1] = *(const uint32_t*)&s.Bl[n][cc + 8];
            }
            #pragma unroll
            for (int mt = 0; mt < 4; mt++)
                #pragma unroll
                for (int nt = 0; nt < 4; nt++) {
                    if (diag && (wm + mt * 16 + 15 < wn + nt * 8)) continue;
                    MMA(acc[mt][nt], Afh[mt], Bfh[nt]);
                    MMA(acc[mt][nt], Afh[mt], Bfl[nt]);
                    MMA(acc[mt][nt], Afl[mt], Bfh[nt]);
                }
        }
        __syncthreads();
    }
}

// ---------------------------------------------------------------- prep
__global__ void k_prep_w(const float* __restrict__ Wq, const float* __restrict__ Wk,
                         const float* __restrict__ Wv) {
    int idx = blockIdx.x * 256 + threadIdx.x;
    int mat = idx >> 16, off = idx & 65535;
    const float* W = (mat == 0) ? Wq : (mat == 1) ? Wk : Wv;
    split2(W[off], g_Wh[idx], g_Wl[idx]);
}

__global__ void k_theta_pe(const float* __restrict__ theta) {
    int idx = blockIdx.x * 256 + threadIdx.x;
    int i = idx & (DIM - 1);
    int l = (idx >> 8) & (LSEQ - 1);
    float expo = (float)(i & ~1) * (1.0f / (float)DIM);
    float ang = (float)l / powf(KAPPA, expo);
    float pe = (i & 1) ? cosf(ang) : sinf(ang);
    split2(theta[idx] + pe, g_TPh[idx], g_TPl[idx]);
}

// ---------------------------------------------------------------- QKV
__global__ void __launch_bounds__(256) k_qkv_mma() {
    extern __shared__ char smraw[];
    Stage* stg = reinterpret_cast<Stage*>(smraw);
    int tid = threadIdx.x;
    int e0 = blockIdx.x * 128, m0 = blockIdx.y * 128, mat = blockIdx.z;

    float acc[4][4][4] = {};
    gemm_main(stg, g_TPh + (size_t)m0 * DIM, g_TPl + (size_t)m0 * DIM, DIM,
              g_Wh + (size_t)mat * 65536 + (size_t)e0 * DIM,
              g_Wl + (size_t)mat * 65536 + (size_t)e0 * DIM, DIM,
              DIM, acc, tid, false);

    int wid = tid >> 5, lane = tid & 31;
    int wm = (wid >> 2) * 64, wn = (wid & 3) * 32;
    int gr = lane >> 2, t4 = lane & 3;
    if (mat == 2) {
        // V: fp16 single-precision path (2-pass PV drops the V-lo term)
        #pragma unroll
        for (int mt = 0; mt < 4; mt++)
            #pragma unroll
            for (int nt = 0; nt < 4; nt++)
                #pragma unroll
                for (int half = 0; half < 2; half++) {
                    int r = m0 + wm + mt * 16 + gr + half * 8;
                    int c = e0 + wn + nt * 8 + 2 * t4;
                    __half2 v2;
                    v2.x = __float2half_rn(acc[mt][nt][half * 2]);
                    v2.y = __float2half_rn(acc[mt][nt][half * 2 + 1]);
                    *(uint32_t*)&g_V16[(size_t)r * DIM + c] = *(uint32_t*)&v2;
                }
    } else {
        bf16* oh = (mat == 0) ? g_Qh : g_Kh;
        bf16* ol = (mat == 0) ? g_Ql : g_Kl;
        #pragma unroll
        for (int mt = 0; mt < 4; mt++)
            #pragma unroll
            for (int nt = 0; nt < 4; nt++)
                #pragma unroll
                for (int half = 0; half < 2; half++) {
                    int r = m0 + wm + mt * 16 + gr + half * 8;
                    int c = e0 + wn + nt * 8 + 2 * t4;
                    __nv_bfloat162 h2, l2;
                    split2(acc[mt][nt][half * 2],     h2.x, l2.x);
                    split2(acc[mt][nt][half * 2 + 1], h2.y, l2.y);
                    *(uint32_t*)&oh[(size_t)r * DIM + c] = *(uint32_t*)&h2;
                    *(uint32_t*)&ol[(size_t)r * DIM + c] = *(uint32_t*)&l2;
                }
    }
}

// ---------------------------------------------------------------- V transpose
__global__ void k_vt() {
    __shared__ __half t[32][33];
    int s0 = blockIdx.x * 32, e0 = blockIdx.y * 32, bh = blockIdx.z;
    int tx = threadIdx.x, ty = threadIdx.y;
    #pragma unroll
    for (int j = 0; j < 4; j++) {
        int sr = s0 + ty + j * 8;
        t[ty + j * 8][tx] = g_V16[((size_t)bh * LSEQ + sr) * DIM + e0 + tx];
    }
    __syncthreads();
    #pragma unroll
    for (int j = 0; j < 4; j++) {
        int e = e0 + ty + j * 8;
        g_VT16[((size_t)bh * DIM + e) * LSEQ + s0 + tx] = t[tx][ty + j * 8];
    }
}

// ---------------------------------------------------------------- scores
__global__ void __launch_bounds__(256) k_scores_mma() {
    int kt = blockIdx.x, qt = blockIdx.y, bh = blockIdx.z;
    if (kt > qt) return;
    extern __shared__ char smraw[];
    Stage* stg = reinterpret_cast<Stage*>(smraw);
    int tid = threadIdx.x;
    int q0 = qt * 128, c0 = kt * 128;
    size_t qb = ((size_t)bh * LSEQ + q0) * DIM;
    size_t kb = ((size_t)bh * LSEQ + c0) * DIM;

    float acc[4][4][4] = {};
    gemm_main(stg, g_Qh + qb, g_Ql + qb, DIM, g_Kh + kb, g_Kl + kb, DIM,
              DIM, acc, tid, kt == qt);

    int wid = tid >> 5, lane = tid & 31;
    int wm = (wid >> 2) * 64, wn = (wid & 3) * 32;
    int gr = lane >> 2, t4 = lane & 3;
    float* S = g_S + (size_t)bh * LSEQ * LSEQ;
    #pragma unroll
    for (int mt = 0; mt < 4; mt++)
        #pragma unroll
        for (int nt = 0; nt < 4; nt++)
            #pragma unroll
            for (int half = 0; half < 2; half++) {
                int r = q0 + wm + mt * 16 + gr + half * 8;
                int c = c0 + wn + nt * 8 + 2 * t4;
                float2 v = make_float2(acc[mt][nt][half * 2] * 0.0625f,
                                       acc[mt][nt][half * 2 + 1] * 0.0625f);
                *(float2*)&S[(size_t)r * LSEQ + c] = v;
            }
}

// ---------------------------------------------------------------- softmax
__global__ void k_softmax() {
    int warp = threadIdx.x >> 5, lane = threadIdx.x & 31;
    int row = blockIdx.x * 8 + warp;
    int bh = row >> 10, q = row & (LSEQ - 1);
    size_t base = (size_t)bh * LSEQ * LSEQ + (size_t)q * LSEQ;
    const float* Srow = g_S + base;
    int len = q + 1;

    float m = -1e30f;
    for (int k = lane; k < len; k += 32) m = fmaxf(m, Srow[k]);
    #pragma unroll
    for (int o = 16; o; o >>= 1) m = fmaxf(m, __shfl_xor_sync(0xFFFFFFFFu, m, o));
    float ssum = 0.0f;
    for (int k = lane; k < len; k += 32) ssum += expf(Srow[k] - m);
    #pragma unroll
    for (int o = 16; o; o >>= 1) ssum += __shfl_xor_sync(0xFFFFFFFFu, ssum, o);
    float inv = 1.0f / ssum;
    for (int k = lane; k < len; k += 32) {
        float p = expf(Srow[k] - m) * inv;
        __half h = __float2half_rn(p);
        __half l = __float2half_rn(p - __half2float(h));
        g_Ph16[base + k] = h; g_Pl16[base + k] = l;
    }
    int end = ((q >> 7) + 1) << 7;
    for (int k = q + 1 + lane; k < end; k += 32) {
        g_Ph16[base + k] = __float2half(0.0f);
        g_Pl16[base + k] = __float2half(0.0f);
    }
}

// ---------------------------------------------------------------- PV (fp16 2-pass)
__global__ void __launch_bounds__(256) k_pv_mma(float* __restrict__ out) {
    int et = blockIdx.x, qt = blockIdx.y, bh = blockIdx.z;
    extern __shared__ char smraw[];
    StageP* stg = reinterpret_cast<StageP*>(smraw);
    int tid = threadIdx.x, wid = tid >> 5, lane = tid & 31;
    int wm = (wid >> 2) * 64, wn = (wid & 3) * 32;
    int gr = lane >> 2, t4 = lane & 3;
    int q0 = qt * 128, e0 = et * 128;
    const __half* Agh = g_Ph16 + (size_t)bh * LSEQ * LSEQ + (size_t)q0 * LSEQ;
    const __half* Agl = g_Pl16 + (size_t)bh * LSEQ * LSEQ + (size_t)q0 * LSEQ;
    const __half* Bg  = g_VT16 + ((size_t)bh * DIM + e0) * LSEQ;
    int nst = (qt + 1) * 4;

    float acc[4][4][4] = {};

    #define LDSTP(ST, K0) do {                                                  \
        int _r = tid >> 2, _c = (tid & 3) * 8;                                  \
        cp16(&(ST).Ah[_r][_c],      Agh + (size_t)_r * LSEQ + (K0) + _c);       \
        cp16(&(ST).Ah[_r + 64][_c], Agh + (size_t)(_r + 64) * LSEQ + (K0) + _c);\
        cp16(&(ST).Al[_r][_c],      Agl + (size_t)_r * LSEQ + (K0) + _c);       \
        cp16(&(ST).Al[_r + 64][_c], Agl + (size_t)(_r + 64) * LSEQ + (K0) + _c);\
        cp16(&(ST).Bh[_r][_c],      Bg  + (size_t)_r * LSEQ + (K0) + _c);       \
        cp16(&(ST).Bh[_r + 64][_c], Bg  + (size_t)(_r + 64) * LSEQ + (K0) + _c);\
        CP_COMMIT();                                                            \
    } while (0)

    LDSTP(stg[0], 0);

    for (int c = 0; c < nst; c++) {
        if (c + 1 < nst) { LDSTP(stg[(c + 1) & 1], (c + 1) * 32); CP_WAIT1(); }
        else             { CP_WAIT0(); }
        __syncthreads();
        StageP& s = stg[c & 1];
        #pragma unroll
        for (int kk = 0; kk < 32; kk += 16) {
            int kabs = c * 32 + kk;
            uint32_t Afh[4][4], Afl[4][4], Bf[4][2];
            bool live[4];
            #pragma unroll
            for (int mt = 0; mt < 4; mt++) {
                live[mt] = (q0 + wm + mt * 16 + 15) >= kabs;   // P rows nonzero?
                if (live[mt]) {
                    int r = wm + mt * 16 + gr, cc = kk + 2 * t4;
                    Afh[mt][0] = *(const uint32_t*)&s.Ah[r][cc];
                    Afh[mt][1] = *(const uint32_t*)&s.Ah[r + 8][cc];
                    Afh[mt][2] = *(const uint32_t*)&s.Ah[r][cc + 8];
                    Afh[mt][3] = *(const uint32_t*)&s.Ah[r + 8][cc + 8];
                    Afl[mt][0] = *(const uint32_t*)&s.Al[r][cc];
                    Afl[mt][1] = *(const uint32_t*)&s.Al[r + 8][cc];
                    Afl[mt][2] = *(const uint32_t*)&s.Al[r][cc + 8];
                    Afl[mt][3] = *(const uint32_t*)&s.Al[r + 8][cc + 8];
                }
            }
            #pragma unroll
            for (int nt = 0; nt < 4; nt++) {
                int n = wn + nt * 8 + gr, cc = kk + 2 * t4;
                Bf[nt][0] = *(const uint32_t*)&s.Bh[n][cc];
                Bf[nt][1] = *(const uint32_t*)&s.Bh[n][cc + 8];
            }
            #pragma unroll
            for (int mt = 0; mt < 4; mt++)
                if (live[mt])
                    #pragma unroll
                    for (int nt = 0; nt < 4; nt++) {
                        MMAH(acc[mt][nt], Afh[mt], Bf[nt]);
                        MMAH(acc[mt][nt], Afl[mt], Bf[nt]);
                    }
        }
        __syncthreads();
    }

    float* O = out + ((size_t)bh * LSEQ + q0) * DIM + e0;
    #pragma unroll
    for (int mt = 0; mt < 4; mt++)
        #pragma unroll
        for (int nt = 0; nt < 4; nt++)
            #pragma unroll
            for (int half = 0; half < 2; half++) {
                int r = wm + mt * 16 + gr + half * 8;
                int c = wn + nt * 8 + 2 * t4;
                float2 v = make_float2(acc[mt][nt][half * 2],
                                       acc[mt][nt][half * 2 + 1]);
                *(float2*)&O[(size_t)r * DIM + c] = v;
            }
}

// ---------------------------------------------------------------- equivariant
__global__ void k_equiv(const float* __restrict__ xi, float* __restrict__ out) {
    __shared__ float xs[LSEQ][3];
    int bh = blockIdx.y;
    int tid = threadIdx.x;
    const float inv23 = 0.0021544346900318843f;

    for (int l = tid; l < LSEQ; l += 128) {
        float fl = (float)l;
        const float* xr = xi + ((size_t)bh * LSEQ + l) * 3;
        xs[l][0] = xr[0] + sinf(fl);
        xs[l][1] = xr[1] + cosf(fl);
        xs[l][2] = xr[2] + sinf(fl * inv23);
    }
    __syncthreads();

    int q = blockIdx.x * 128 + tid;
    float qx = xs[q][0], qy = xs[q][1], qz = xs[q][2];
    float m = -1e30f, denom = 0.0f, wn = 0.0f;
    float n0 = 0.0f, n1 = 0.0f, n2 = 0.0f;
    for (int k = 0; k <= q; k++) {
        float dx = qx - xs[k][0], dy = qy - xs[k][1], dz = qz - xs[k][2];
        float sq = dx * dx + dy * dy + dz * dz;
        if (sq > m) {
            float sc = expf(m - sq);
            denom *= sc; wn *= sc; n0 *= sc; n1 *= sc; n2 *= sc;
            m = sq;
        }
        float e = expf(sq - m);
        denom += e;
        if (k != q) { wn += e; n0 += e * xs[k][0]; n1 += e * xs[k][1]; n2 += e * xs[k][2]; }
    }
    float invd = 1.0f / denom;
    float bw = 0.5f * wn * invd;
    float* o = out + X_OFF + ((size_t)bh * LSEQ + q) * 3;
    o[0] = qx + 0.5f * n0 * invd - bw * qx;
    o[1] = qy + 0.5f * n1 * invd - bw * qy;
    o[2] = qz + 0.5f * n2 * invd - bw * qz;
}

// ---------------------------------------------------------------- edge
__global__ void k_edge(const float* __restrict__ edge, float* __restrict__ out) {
    int idx = blockIdx.x * 256 + threadIdx.x;
    int c = idx % EDGE_C;
    int l = (idx / EDGE_C) & (LSEQ - 1);
    float expo = (float)(c & ~1) * (1.0f / (float)EDGE_C);
    float ang = (float)l / powf(KAPPA, expo);
    float pe = (c & 1) ? cosf(ang) : sinf(ang);
    out[E_OFF + idx] = edge[idx] + pe;
}

// ----------------------------------------------------------------------------
extern "C" void kernel_launch(void* const* d_in, const int* in_sizes, int n_in,
                              void* d_out, int out_size) {
    const float* theta = (const float*)d_in[0];
    const float* xi    = (const float*)d_in[1];
    const float* edge  = (const float*)d_in[2];
    const float* Wq    = (const float*)d_in[3];
    const float* Wk    = (const float*)d_in[4];
    const float* Wv    = (const float*)d_in[5];
    float* out = (float*)d_out;

    static bool attr_done = false;
    if (!attr_done) {
        cudaFuncSetAttribute(k_qkv_mma,    cudaFuncAttributeMaxDynamicSharedMemorySize, (int)SMEM_DYN);
        cudaFuncSetAttribute(k_scores_mma, cudaFuncAttributeMaxDynamicSharedMemorySize, (int)SMEM_DYN);
        cudaFuncSetAttribute(k_pv_mma,     cudaFuncAttributeMaxDynamicSharedMemorySize, (int)SMEM_PV);
        attr_done = true;
    }

    k_prep_w<<<(3 * DIM * DIM) / 256, 256>>>(Wq, Wk, Wv);
    k_theta_pe<<<H_ELEMS / 256, 256>>>(theta);
    k_qkv_mma<<<dim3(2, 256, 3), 256, SMEM_DYN>>>();
    k_vt<<<dim3(32, 8, 32), dim3(32, 8)>>>();
    k_scores_mma<<<dim3(8, 8, BH), 256, SMEM_DYN>>>();
    k_softmax<<<(BH * LSEQ) / 8, 256>>>();
    k_pv_mma<<<dim3(2, 8, BH), 256, SMEM_PV>>>(out);
    k_equiv<<<dim3(8, BH), 128>>>(xi, out);
    k_edge<<<E_ELEMS / 256, 256>>>(edge, out);
}

// round 10
// speedup vs baseline: 1.3514x; 1.1333x over previous
#include <cuda_runtime.h>
#include <cuda_fp16.h>
#include <math.h>
#include <stdint.h>

// ---------------------------------------------------------------- constants
#define LSEQ 1024
#define DIM  256
#define BH   32          // B*N heads
#define EDGE_C 112
#define KAPPA 10000.0f

#define H_ELEMS  (BH * LSEQ * DIM)
#define X_ELEMS  (BH * LSEQ * 3)
#define E_ELEMS  (4 * LSEQ * EDGE_C)
#define X_OFF    H_ELEMS
#define E_OFF    (H_ELEMS + X_ELEMS)

// ---------------------------------------------------------------- scratch
__device__ __align__(16) __half g_TPh[H_ELEMS], g_TPl[H_ELEMS];    // theta+PE split
__device__ __align__(16) __half g_W16[3 * DIM * DIM];              // W (fp16)
__device__ __align__(16) __half g_Qh[H_ELEMS], g_Ql[H_ELEMS];      // Q split
__device__ __align__(16) __half g_K16[H_ELEMS];                    // K (fp16)
__device__ __align__(16) __half g_V16[H_ELEMS];                    // V (fp16)
__device__ __align__(16) __half g_VT16[H_ELEMS];                   // [bh][e][s]
__device__ __align__(16) float g_S[(size_t)BH * LSEQ * LSEQ];
__device__ __align__(16) __half g_Ph16[(size_t)BH * LSEQ * LSEQ];
__device__ __align__(16) __half g_Pl16[(size_t)BH * LSEQ * LSEQ];

__device__ __forceinline__ void hsplit(float v, __half& h, __half& l) {
    h = __float2half_rn(v);
    l = __float2half_rn(v - __half2float(h));
}

// ---------------------------------------------------------------- MMA core
#define MMAH(acc, af, bf)                                                       \
    asm volatile(                                                               \
        "mma.sync.aligned.m16n8k16.row.col.f32.f16.f16.f32 "                    \
        "{%0,%1,%2,%3}, {%4,%5,%6,%7}, {%8,%9}, {%0,%1,%2,%3};"                 \
        : "+f"((acc)[0]), "+f"((acc)[1]), "+f"((acc)[2]), "+f"((acc)[3])        \
        : "r"((af)[0]), "r"((af)[1]), "r"((af)[2]), "r"((af)[3]),               \
          "r"((bf)[0]), "r"((bf)[1]))

#define KPAD 40   // 32 k + 8 pad: 80B row stride (16B aligned for cp.async)

struct StageP {
    __half Ah[128][KPAD], Al[128][KPAD], Bh[128][KPAD];
};
#define SMEM_PV (2 * sizeof(StageP))   // 61440 B -> 3 blocks/SM

__device__ __forceinline__ void cp16(void* dst, const void* src) {
    uint32_t d = (uint32_t)__cvta_generic_to_shared(dst);
    asm volatile("cp.async.cg.shared.global [%0], [%1], 16;" :: "r"(d), "l"(src));
}
#define CP_COMMIT() asm volatile("cp.async.commit_group;" ::: "memory")
#define CP_WAIT1()  asm volatile("cp.async.wait_group 1;" ::: "memory")
#define CP_WAIT0()  asm volatile("cp.async.wait_group 0;" ::: "memory")

// Stage A-hi, A-lo, B (3 x 128x32 fp16 slices; 256 threads, 6 x 16B each).
#define LDSTP(ST, K0) do {                                                      \
    int _r = tid >> 2, _c = (tid & 3) * 8;                                      \
    cp16(&(ST).Ah[_r][_c],      Agh + (size_t)_r * lda + (K0) + _c);            \
    cp16(&(ST).Ah[_r + 64][_c], Agh + (size_t)(_r + 64) * lda + (K0) + _c);     \
    cp16(&(ST).Al[_r][_c],      Agl + (size_t)_r * lda + (K0) + _c);            \
    cp16(&(ST).Al[_r + 64][_c], Agl + (size_t)(_r + 64) * lda + (K0) + _c);     \
    cp16(&(ST).Bh[_r][_c],      Bg  + (size_t)_r * ldb + (K0) + _c);            \
    cp16(&(ST).Bh[_r + 64][_c], Bg  + (size_t)(_r + 64) * ldb + (K0) + _c);     \
    CP_COMMIT();                                                                \
} while (0)

// Unified fp16 2-pass GEMM: D = (Ah+Al) * B^T.
//   diag:   skip microtiles fully above the diagonal (scores diagonal block)
//   pvskip: skip mt microtiles whose A rows are all-zero (causal P, q0 = row base)
__device__ __forceinline__ void gemm2(
    StageP* stg,
    const __half* __restrict__ Agh, const __half* __restrict__ Agl, int lda,
    const __half* __restrict__ Bg, int ldb,
    int K, float acc[4][4][4], int tid, bool diag, bool pvskip, int q0)
{
    int wid = tid >> 5, lane = tid & 31;
    int wm = (wid >> 2) * 64, wn = (wid & 3) * 32;
    int gr = lane >> 2, t4 = lane & 3;
    int nst = K >> 5;

    LDSTP(stg[0], 0);

    for (int c = 0; c < nst; c++) {
        if (c + 1 < nst) { LDSTP(stg[(c + 1) & 1], (c + 1) * 32); CP_WAIT1(); }
        else             { CP_WAIT0(); }
        __syncthreads();
        StageP& s = stg[c & 1];
        #pragma unroll
        for (int kk = 0; kk < 32; kk += 16) {
            int kabs = c * 32 + kk;
            uint32_t Afh[4][4], Afl[4][4], Bf[4][2];
            bool live[4];
            #pragma unroll
            for (int mt = 0; mt < 4; mt++) {
                live[mt] = !pvskip || ((q0 + wm + mt * 16 + 15) >= kabs);
                if (live[mt]) {
                    int r = wm + mt * 16 + gr, cc = kk + 2 * t4;
                    Afh[mt][0] = *(const uint32_t*)&s.Ah[r][cc];
                    Afh[mt][1] = *(const uint32_t*)&s.Ah[r + 8][cc];
                    Afh[mt][2] = *(const uint32_t*)&s.Ah[r][cc + 8];
                    Afh[mt][3] = *(const uint32_t*)&s.Ah[r + 8][cc + 8];
                    Afl[mt][0] = *(const uint32_t*)&s.Al[r][cc];
                    Afl[mt][1] = *(const uint32_t*)&s.Al[r + 8][cc];
                    Afl[mt][2] = *(const uint32_t*)&s.Al[r][cc + 8];
                    Afl[mt][3] = *(const uint32_t*)&s.Al[r + 8][cc + 8];
                }
            }
            #pragma unroll
            for (int nt = 0; nt < 4; nt++) {
                int n = wn + nt * 8 + gr, cc = kk + 2 * t4;
                Bf[nt][0] = *(const uint32_t*)&s.Bh[n][cc];
                Bf[nt][1] = *(const uint32_t*)&s.Bh[n][cc + 8];
            }
            #pragma unroll
            for (int mt = 0; mt < 4; mt++)
                if (live[mt])
                    #pragma unroll
                    for (int nt = 0; nt < 4; nt++) {
                        if (diag && (wm + mt * 16 + 15 < wn + nt * 8)) continue;
                        MMAH(acc[mt][nt], Afh[mt], Bf[nt]);
                        MMAH(acc[mt][nt], Afl[mt], Bf[nt]);
                    }
        }
        __syncthreads();
    }
}

// ---------------------------------------------------------------- prep
__global__ void k_prep_w(const float* __restrict__ Wq, const float* __restrict__ Wk,
                         const float* __restrict__ Wv) {
    int idx = blockIdx.x * 256 + threadIdx.x;
    int mat = idx >> 16, off = idx & 65535;
    const float* W = (mat == 0) ? Wq : (mat == 1) ? Wk : Wv;
    g_W16[idx] = __float2half_rn(W[off]);
}

__global__ void k_theta_pe(const float* __restrict__ theta) {
    int idx = blockIdx.x * 256 + threadIdx.x;
    int i = idx & (DIM - 1);
    int l = (idx >> 8) & (LSEQ - 1);
    float expo = (float)(i & ~1) * (1.0f / (float)DIM);
    float ang = (float)l / powf(KAPPA, expo);
    float pe = (i & 1) ? cosf(ang) : sinf(ang);
    hsplit(theta[idx] + pe, g_TPh[idx], g_TPl[idx]);
}

// ---------------------------------------------------------------- QKV
__global__ void __launch_bounds__(256) k_qkv_mma() {
    extern __shared__ char smraw[];
    StageP* stg = reinterpret_cast<StageP*>(smraw);
    int tid = threadIdx.x;
    int e0 = blockIdx.x * 128, m0 = blockIdx.y * 128, mat = blockIdx.z;

    float acc[4][4][4] = {};
    gemm2(stg, g_TPh + (size_t)m0 * DIM, g_TPl + (size_t)m0 * DIM, DIM,
          g_W16 + (size_t)mat * 65536 + (size_t)e0 * DIM, DIM,
          DIM, acc, tid, false, false, 0);

    int wid = tid >> 5, lane = tid & 31;
    int wm = (wid >> 2) * 64, wn = (wid & 3) * 32;
    int gr = lane >> 2, t4 = lane & 3;
    if (mat == 0) {
        // Q: fp16 hi/lo split (A operand of scores 2-pass)
        #pragma unroll
        for (int mt = 0; mt < 4; mt++)
            #pragma unroll
            for (int nt = 0; nt < 4; nt++)
                #pragma unroll
                for (int half = 0; half < 2; half++) {
                    int r = m0 + wm + mt * 16 + gr + half * 8;
                    int c = e0 + wn + nt * 8 + 2 * t4;
                    __half2 h2, l2;
                    hsplit(acc[mt][nt][half * 2],     h2.x, l2.x);
                    hsplit(acc[mt][nt][half * 2 + 1], h2.y, l2.y);
                    *(uint32_t*)&g_Qh[(size_t)r * DIM + c] = *(uint32_t*)&h2;
                    *(uint32_t*)&g_Ql[(size_t)r * DIM + c] = *(uint32_t*)&l2;
                }
    } else {
        // K / V: single fp16 (B operands)
        __half* o = (mat == 1) ? g_K16 : g_V16;
        #pragma unroll
        for (int mt = 0; mt < 4; mt++)
            #pragma unroll
            for (int nt = 0; nt < 4; nt++)
                #pragma unroll
                for (int half = 0; half < 2; half++) {
                    int r = m0 + wm + mt * 16 + gr + half * 8;
                    int c = e0 + wn + nt * 8 + 2 * t4;
                    __half2 v2;
                    v2.x = __float2half_rn(acc[mt][nt][half * 2]);
                    v2.y = __float2half_rn(acc[mt][nt][half * 2 + 1]);
                    *(uint32_t*)&o[(size_t)r * DIM + c] = *(uint32_t*)&v2;
                }
    }
}

// ---------------------------------------------------------------- V transpose
__global__ void k_vt() {
    __shared__ __half t[32][33];
    int s0 = blockIdx.x * 32, e0 = blockIdx.y * 32, bh = blockIdx.z;
    int tx = threadIdx.x, ty = threadIdx.y;
    #pragma unroll
    for (int j = 0; j < 4; j++) {
        int sr = s0 + ty + j * 8;
        t[ty + j * 8][tx] = g_V16[((size_t)bh * LSEQ + sr) * DIM + e0 + tx];
    }
    __syncthreads();
    #pragma unroll
    for (int j = 0; j < 4; j++) {
        int e = e0 + ty + j * 8;
        g_VT16[((size_t)bh * DIM + e) * LSEQ + s0 + tx] = t[tx][ty + j * 8];
    }
}

// ---------------------------------------------------------------- scores
__global__ void __launch_bounds__(256) k_scores_mma() {
    int kt = blockIdx.x, qt = blockIdx.y, bh = blockIdx.z;
    if (kt > qt) return;
    extern __shared__ char smraw[];
    StageP* stg = reinterpret_cast<StageP*>(smraw);
    int tid = threadIdx.x;
    int q0 = qt * 128, c0 = kt * 128;
    size_t qb = ((size_t)bh * LSEQ + q0) * DIM;
    size_t kb = ((size_t)bh * LSEQ + c0) * DIM;

    float acc[4][4][4] = {};
    gemm2(stg, g_Qh + qb, g_Ql + qb, DIM, g_K16 + kb, DIM,
          DIM, acc, tid, kt == qt, false, 0);

    int wid = tid >> 5, lane = tid & 31;
    int wm = (wid >> 2) * 64, wn = (wid & 3) * 32;
    int gr = lane >> 2, t4 = lane & 3;
    float* S = g_S + (size_t)bh * LSEQ * LSEQ;
    #pragma unroll
    for (int mt = 0; mt < 4; mt++)
        #pragma unroll
        for (int nt = 0; nt < 4; nt++)
            #pragma unroll
            for (int half = 0; half < 2; half++) {
                int r = q0 + wm + mt * 16 + gr + half * 8;
                int c = c0 + wn + nt * 8 + 2 * t4;
                float2 v = make_float2(acc[mt][nt][half * 2] * 0.0625f,
                                       acc[mt][nt][half * 2 + 1] * 0.0625f);
                *(float2*)&S[(size_t)r * LSEQ + c] = v;
            }
}

// ---------------------------------------------------------------- softmax
__global__ void k_softmax() {
    int warp = threadIdx.x >> 5, lane = threadIdx.x & 31;
    int row = blockIdx.x * 8 + warp;
    int bh = row >> 10, q = row & (LSEQ - 1);
    size_t base = (size_t)bh * LSEQ * LSEQ + (size_t)q * LSEQ;
    const float* Srow = g_S + base;
    int len = q + 1;

    float m = -1e30f;
    for (int k = lane; k < len; k += 32) m = fmaxf(m, Srow[k]);
    #pragma unroll
    for (int o = 16; o; o >>= 1) m = fmaxf(m, __shfl_xor_sync(0xFFFFFFFFu, m, o));
    float ssum = 0.0f;
    for (int k = lane; k < len; k += 32) ssum += expf(Srow[k] - m);
    #pragma unroll
    for (int o = 16; o; o >>= 1) ssum += __shfl_xor_sync(0xFFFFFFFFu, ssum, o);
    float inv = 1.0f / ssum;
    for (int k = lane; k < len; k += 32) {
        float p = expf(Srow[k] - m) * inv;
        __half h, l; hsplit(p, h, l);
        g_Ph16[base + k] = h; g_Pl16[base + k] = l;
    }
    int end = ((q >> 7) + 1) << 7;
    for (int k = q + 1 + lane; k < end; k += 32) {
        g_Ph16[base + k] = __float2half(0.0f);
        g_Pl16[base + k] = __float2half(0.0f);
    }
}

// ---------------------------------------------------------------- PV
__global__ void __launch_bounds__(256) k_pv_mma(float* __restrict__ out) {
    int et = blockIdx.x, qt = blockIdx.y, bh = blockIdx.z;
    extern __shared__ char smraw[];
    StageP* stg = reinterpret_cast<StageP*>(smraw);
    int tid = threadIdx.x;
    int q0 = qt * 128, e0 = et * 128;
    size_t pb = (size_t)bh * LSEQ * LSEQ + (size_t)q0 * LSEQ;
    size_t vb = ((size_t)bh * DIM + e0) * LSEQ;

    float acc[4][4][4] = {};
    gemm2(stg, g_Ph16 + pb, g_Pl16 + pb, LSEQ, g_VT16 + vb, LSEQ,
          (qt + 1) * 128, acc, tid, false, true, q0);

    int wid = tid >> 5, lane = tid & 31;
    int wm = (wid >> 2) * 64, wn = (wid & 3) * 32;
    int gr = lane >> 2, t4 = lane & 3;
    float* O = out + ((size_t)bh * LSEQ + q0) * DIM + e0;
    #pragma unroll
    for (int mt = 0; mt < 4; mt++)
        #pragma unroll
        for (int nt = 0; nt < 4; nt++)
            #pragma unroll
            for (int half = 0; half < 2; half++) {
                int r = wm + mt * 16 + gr + half * 8;
                int c = wn + nt * 8 + 2 * t4;
                float2 v = make_float2(acc[mt][nt][half * 2],
                                       acc[mt][nt][half * 2 + 1]);
                *(float2*)&O[(size_t)r * DIM + c] = v;
            }
}

// ---------------------------------------------------------------- equivariant
__global__ void k_equiv(const float* __restrict__ xi, float* __restrict__ out) {
    __shared__ float xs[LSEQ][3];
    int bh = blockIdx.y;
    int tid = threadIdx.x;
    const float inv23 = 0.0021544346900318843f;

    for (int l = tid; l < LSEQ; l += 128) {
        float fl = (float)l;
        const float* xr = xi + ((size_t)bh * LSEQ + l) * 3;
        xs[l][0] = xr[0] + sinf(fl);
        xs[l][1] = xr[1] + cosf(fl);
        xs[l][2] = xr[2] + sinf(fl * inv23);
    }
    __syncthreads();

    int q = blockIdx.x * 128 + tid;
    float qx = xs[q][0], qy = xs[q][1], qz = xs[q][2];
    float m = -1e30f, denom = 0.0f, wn = 0.0f;
    float n0 = 0.0f, n1 = 0.0f, n2 = 0.0f;
    for (int k = 0; k <= q; k++) {
        float dx = qx - xs[k][0], dy = qy - xs[k][1], dz = qz - xs[k][2];
        float sq = dx * dx + dy * dy + dz * dz;
        if (sq > m) {
            float sc = expf(m - sq);
            denom *= sc; wn *= sc; n0 *= sc; n1 *= sc; n2 *= sc;
            m = sq;
        }
        float e = expf(sq - m);
        denom += e;
        if (k != q) { wn += e; n0 += e * xs[k][0]; n1 += e * xs[k][1]; n2 += e * xs[k][2]; }
    }
    float invd = 1.0f / denom;
    float bw = 0.5f * wn * invd;
    float* o = out + X_OFF + ((size_t)bh * LSEQ + q) * 3;
    o[0] = qx + 0.5f * n0 * invd - bw * qx;
    o[1] = qy + 0.5f * n1 * invd - bw * qy;
    o[2] = qz + 0.5f * n2 * invd - bw * qz;
}

// ---------------------------------------------------------------- edge
__global__ void k_edge(const float* __restrict__ edge, float* __restrict__ out) {
    int idx = blockIdx.x * 256 + threadIdx.x;
    int c = idx % EDGE_C;
    int l = (idx / EDGE_C) & (LSEQ - 1);
    float expo = (float)(c & ~1) * (1.0f / (float)EDGE_C);
    float ang = (float)l / powf(KAPPA, expo);
    float pe = (c & 1) ? cosf(ang) : sinf(ang);
    out[E_OFF + idx] = edge[idx] + pe;
}

// ----------------------------------------------------------------------------
extern "C" void kernel_launch(void* const* d_in, const int* in_sizes, int n_in,
                              void* d_out, int out_size) {
    const float* theta = (const float*)d_in[0];
    const float* xi    = (const float*)d_in[1];
    const float* edge  = (const float*)d_in[2];
    const float* Wq    = (const float*)d_in[3];
    const float* Wk    = (const float*)d_in[4];
    const float* Wv    = (const float*)d_in[5];
    float* out = (float*)d_out;

    static bool attr_done = false;
    if (!attr_done) {
        cudaFuncSetAttribute(k_qkv_mma,    cudaFuncAttributeMaxDynamicSharedMemorySize, (int)SMEM_PV);
        cudaFuncSetAttribute(k_scores_mma, cudaFuncAttributeMaxDynamicSharedMemorySize, (int)SMEM_PV);
        cudaFuncSetAttribute(k_pv_mma,     cudaFuncAttributeMaxDynamicSharedMemorySize, (int)SMEM_PV);
        attr_done = true;
    }

    k_prep_w<<<(3 * DIM * DIM) / 256, 256>>>(Wq, Wk, Wv);
    k_theta_pe<<<H_ELEMS / 256, 256>>>(theta);
    k_qkv_mma<<<dim3(2, 256, 3), 256, SMEM_PV>>>();
    k_vt<<<dim3(32, 8, 32), dim3(32, 8)>>>();
    k_scores_mma<<<dim3(8, 8, BH), 256, SMEM_PV>>>();
    k_softmax<<<(BH * LSEQ) / 8, 256>>>();
    k_pv_mma<<<dim3(2, 8, BH), 256, SMEM_PV>>>(out);
    k_equiv<<<dim3(8, BH), 128>>>(xi, out);
    k_edge<<<E_ELEMS / 256, 256>>>(edge, out);
}

// round 12
// speedup vs baseline: 1.4723x; 1.0895x over previous
#include <cuda_runtime.h>
#include <cuda_fp16.h>
#include <math.h>
#include <stdint.h>

// ---------------------------------------------------------------- constants
#define LSEQ 1024
#define DIM  256
#define BH   32          // B*N heads
#define EDGE_C 112
#define KAPPA 10000.0f

#define H_ELEMS  (BH * LSEQ * DIM)
#define X_ELEMS  (BH * LSEQ * 3)
#define E_ELEMS  (4 * LSEQ * EDGE_C)
#define X_OFF    H_ELEMS
#define E_OFF    (H_ELEMS + X_ELEMS)

// ---------------------------------------------------------------- scratch
__device__ __align__(16) __half g_TPh[H_ELEMS], g_TPl[H_ELEMS];    // theta+PE split
__device__ __align__(16) __half g_W16[3 * DIM * DIM];              // W (fp16)
__device__ __align__(16) __half g_Qh[H_ELEMS], g_Ql[H_ELEMS];      // Q split
__device__ __align__(16) __half g_K16[H_ELEMS];                    // K (fp16)
__device__ __align__(16) __half g_V16[H_ELEMS];                    // V (fp16)
__device__ __align__(16) __half g_VT16[H_ELEMS];                   // [bh][e][s]
__device__ __align__(16) float g_S[(size_t)BH * LSEQ * LSEQ];
__device__ __align__(16) __half g_Ph16[(size_t)BH * LSEQ * LSEQ];  // P (fp16)

__device__ __forceinline__ void hsplit(float v, __half& h, __half& l) {
    h = __float2half_rn(v);
    l = __float2half_rn(v - __half2float(h));
}

// ---------------------------------------------------------------- MMA core
#define MMAH(acc, af, bf)                                                       \
    asm volatile(                                                               \
        "mma.sync.aligned.m16n8k16.row.col.f32.f16.f16.f32 "                    \
        "{%0,%1,%2,%3}, {%4,%5,%6,%7}, {%8,%9}, {%0,%1,%2,%3};"                 \
        : "+f"((acc)[0]), "+f"((acc)[1]), "+f"((acc)[2]), "+f"((acc)[3])        \
        : "r"((af)[0]), "r"((af)[1]), "r"((af)[2]), "r"((af)[3]),               \
          "r"((bf)[0]), "r"((bf)[1]))

#define KPAD 40   // 32 k + 8 pad: 80B row stride (16B aligned for cp.async)

struct StageP {                 // QKV / scores: A split + B
    __half Ah[128][KPAD], Al[128][KPAD], Bh[128][KPAD];
};
#define SMEM_G2 (2 * sizeof(StageP))   // 61440 B

struct StageV {                 // PV: A + B only
    __half Ah[128][KPAD], Bh[128][KPAD];
};
#define SMEM_PV (2 * sizeof(StageV))   // 40960 B

__device__ __forceinline__ void cp16(void* dst, const void* src) {
    uint32_t d = (uint32_t)__cvta_generic_to_shared(dst);
    asm volatile("cp.async.cg.shared.global [%0], [%1], 16;" :: "r"(d), "l"(src));
}
#define CP_COMMIT() asm volatile("cp.async.commit_group;" ::: "memory")
#define CP_WAIT1()  asm volatile("cp.async.wait_group 1;" ::: "memory")
#define CP_WAIT0()  asm volatile("cp.async.wait_group 0;" ::: "memory")

// Stage A-hi, A-lo, B (3 x 128x32 fp16 slices; 256 threads, 6 x 16B each).
#define LDSTP(ST, K0) do {                                                      \
    int _r = tid >> 2, _c = (tid & 3) * 8;                                      \
    cp16(&(ST).Ah[_r][_c],      Agh + (size_t)_r * lda + (K0) + _c);            \
    cp16(&(ST).Ah[_r + 64][_c], Agh + (size_t)(_r + 64) * lda + (K0) + _c);     \
    cp16(&(ST).Al[_r][_c],      Agl + (size_t)_r * lda + (K0) + _c);            \
    cp16(&(ST).Al[_r + 64][_c], Agl + (size_t)(_r + 64) * lda + (K0) + _c);     \
    cp16(&(ST).Bh[_r][_c],      Bg  + (size_t)_r * ldb + (K0) + _c);            \
    cp16(&(ST).Bh[_r + 64][_c], Bg  + (size_t)(_r + 64) * ldb + (K0) + _c);     \
    CP_COMMIT();                                                                \
} while (0)

// fp16 2-pass GEMM: D = (Ah+Al) * B^T.  diag: skip microtiles above diagonal.
__device__ __forceinline__ void gemm2(
    StageP* stg,
    const __half* __restrict__ Agh, const __half* __restrict__ Agl, int lda,
    const __half* __restrict__ Bg, int ldb,
    int K, float acc[4][4][4], int tid, bool diag)
{
    int wid = tid >> 5, lane = tid & 31;
    int wm = (wid >> 2) * 64, wn = (wid & 3) * 32;
    int gr = lane >> 2, t4 = lane & 3;
    int nst = K >> 5;

    LDSTP(stg[0], 0);

    for (int c = 0; c < nst; c++) {
        if (c + 1 < nst) { LDSTP(stg[(c + 1) & 1], (c + 1) * 32); CP_WAIT1(); }
        else             { CP_WAIT0(); }
        __syncthreads();
        StageP& s = stg[c & 1];
        #pragma unroll
        for (int kk = 0; kk < 32; kk += 16) {
            uint32_t Afh[4][4], Afl[4][4], Bf[4][2];
            #pragma unroll
            for (int mt = 0; mt < 4; mt++) {
                int r = wm + mt * 16 + gr, cc = kk + 2 * t4;
                Afh[mt][0] = *(const uint32_t*)&s.Ah[r][cc];
                Afh[mt][1] = *(const uint32_t*)&s.Ah[r + 8][cc];
                Afh[mt][2] = *(const uint32_t*)&s.Ah[r][cc + 8];
                Afh[mt][3] = *(const uint32_t*)&s.Ah[r + 8][cc + 8];
                Afl[mt][0] = *(const uint32_t*)&s.Al[r][cc];
                Afl[mt][1] = *(const uint32_t*)&s.Al[r + 8][cc];
                Afl[mt][2] = *(const uint32_t*)&s.Al[r][cc + 8];
                Afl[mt][3] = *(const uint32_t*)&s.Al[r + 8][cc + 8];
            }
            #pragma unroll
            for (int nt = 0; nt < 4; nt++) {
                int n = wn + nt * 8 + gr, cc = kk + 2 * t4;
                Bf[nt][0] = *(const uint32_t*)&s.Bh[n][cc];
                Bf[nt][1] = *(const uint32_t*)&s.Bh[n][cc + 8];
            }
            #pragma unroll
            for (int mt = 0; mt < 4; mt++)
                #pragma unroll
                for (int nt = 0; nt < 4; nt++) {
                    if (diag && (wm + mt * 16 + 15 < wn + nt * 8)) continue;
                    MMAH(acc[mt][nt], Afh[mt], Bf[nt]);
                    MMAH(acc[mt][nt], Afl[mt], Bf[nt]);
                }
        }
        __syncthreads();
    }
}

// ---------------------------------------------------------------- prep
__global__ void k_prep_w(const float* __restrict__ Wq, const float* __restrict__ Wk,
                         const float* __restrict__ Wv) {
    int idx = blockIdx.x * 256 + threadIdx.x;
    int mat = idx >> 16, off = idx & 65535;
    const float* W = (mat == 0) ? Wq : (mat == 1) ? Wk : Wv;
    g_W16[idx] = __float2half_rn(W[off]);
}

__global__ void k_theta_pe(const float* __restrict__ theta) {
    int idx = blockIdx.x * 256 + threadIdx.x;
    int i = idx & (DIM - 1);
    int l = (idx >> 8) & (LSEQ - 1);
    float expo = (float)(i & ~1) * (1.0f / (float)DIM);
    float ang = (float)l / powf(KAPPA, expo);
    float pe = (i & 1) ? cosf(ang) : sinf(ang);
    hsplit(theta[idx] + pe, g_TPh[idx], g_TPl[idx]);
}

// ---------------------------------------------------------------- QKV
__global__ void __launch_bounds__(256) k_qkv_mma() {
    extern __shared__ char smraw[];
    StageP* stg = reinterpret_cast<StageP*>(smraw);
    int tid = threadIdx.x;
    int e0 = blockIdx.x * 128, m0 = blockIdx.y * 128, mat = blockIdx.z;

    float acc[4][4][4] = {};
    gemm2(stg, g_TPh + (size_t)m0 * DIM, g_TPl + (size_t)m0 * DIM, DIM,
          g_W16 + (size_t)mat * 65536 + (size_t)e0 * DIM, DIM,
          DIM, acc, tid, false);

    int wid = tid >> 5, lane = tid & 31;
    int wm = (wid >> 2) * 64, wn = (wid & 3) * 32;
    int gr = lane >> 2, t4 = lane & 3;
    if (mat == 0) {
        // Q: fp16 hi/lo split (A operand of scores 2-pass)
        #pragma unroll
        for (int mt = 0; mt < 4; mt++)
            #pragma unroll
            for (int nt = 0; nt < 4; nt++)
                #pragma unroll
                for (int half = 0; half < 2; half++) {
                    int r = m0 + wm + mt * 16 + gr + half * 8;
                    int c = e0 + wn + nt * 8 + 2 * t4;
                    __half2 h2, l2;
                    hsplit(acc[mt][nt][half * 2],     h2.x, l2.x);
                    hsplit(acc[mt][nt][half * 2 + 1], h2.y, l2.y);
                    *(uint32_t*)&g_Qh[(size_t)r * DIM + c] = *(uint32_t*)&h2;
                    *(uint32_t*)&g_Ql[(size_t)r * DIM + c] = *(uint32_t*)&l2;
                }
    } else {
        // K / V: single fp16 (B operands)
        __half* o = (mat == 1) ? g_K16 : g_V16;
        #pragma unroll
        for (int mt = 0; mt < 4; mt++)
            #pragma unroll
            for (int nt = 0; nt < 4; nt++)
                #pragma unroll
                for (int half = 0; half < 2; half++) {
                    int r = m0 + wm + mt * 16 + gr + half * 8;
                    int c = e0 + wn + nt * 8 + 2 * t4;
                    __half2 v2;
                    v2.x = __float2half_rn(acc[mt][nt][half * 2]);
                    v2.y = __float2half_rn(acc[mt][nt][half * 2 + 1]);
                    *(uint32_t*)&o[(size_t)r * DIM + c] = *(uint32_t*)&v2;
                }
    }
}

// ---------------------------------------------------------------- V transpose
__global__ void k_vt() {
    __shared__ __half t[32][33];
    int s0 = blockIdx.x * 32, e0 = blockIdx.y * 32, bh = blockIdx.z;
    int tx = threadIdx.x, ty = threadIdx.y;
    #pragma unroll
    for (int j = 0; j < 4; j++) {
        int sr = s0 + ty + j * 8;
        t[ty + j * 8][tx] = g_V16[((size_t)bh * LSEQ + sr) * DIM + e0 + tx];
    }
    __syncthreads();
    #pragma unroll
    for (int j = 0; j < 4; j++) {
        int e = e0 + ty + j * 8;
        g_VT16[((size_t)bh * DIM + e) * LSEQ + s0 + tx] = t[tx][ty + j * 8];
    }
}

// ---------------------------------------------------------------- scores
__global__ void __launch_bounds__(256) k_scores_mma() {
    int kt = blockIdx.x, qt = blockIdx.y, bh = blockIdx.z;
    if (kt > qt) return;
    extern __shared__ char smraw[];
    StageP* stg = reinterpret_cast<StageP*>(smraw);
    int tid = threadIdx.x;
    int q0 = qt * 128, c0 = kt * 128;
    size_t qb = ((size_t)bh * LSEQ + q0) * DIM;
    size_t kb = ((size_t)bh * LSEQ + c0) * DIM;

    float acc[4][4][4] = {};
    gemm2(stg, g_Qh + qb, g_Ql + qb, DIM, g_K16 + kb, DIM,
          DIM, acc, tid, kt == qt);

    int wid = tid >> 5, lane = tid & 31;
    int wm = (wid >> 2) * 64, wn = (wid & 3) * 32;
    int gr = lane >> 2, t4 = lane & 3;
    float* S = g_S + (size_t)bh * LSEQ * LSEQ;
    #pragma unroll
    for (int mt = 0; mt < 4; mt++)
        #pragma unroll
        for (int nt = 0; nt < 4; nt++)
            #pragma unroll
            for (int half = 0; half < 2; half++) {
                int r = q0 + wm + mt * 16 + gr + half * 8;
                int c = c0 + wn + nt * 8 + 2 * t4;
                float2 v = make_float2(acc[mt][nt][half * 2] * 0.0625f,
                                       acc[mt][nt][half * 2 + 1] * 0.0625f);
                *(float2*)&S[(size_t)r * LSEQ + c] = v;
            }
}

// ---------------------------------------------------------------- softmax
__global__ void k_softmax() {
    int warp = threadIdx.x >> 5, lane = threadIdx.x & 31;
    int row = blockIdx.x * 8 + warp;
    int bh = row >> 10, q = row & (LSEQ - 1);
    size_t base = (size_t)bh * LSEQ * LSEQ + (size_t)q * LSEQ;
    const float* Srow = g_S + base;
    int len = q + 1;

    float m = -1e30f;
    for (int k = lane; k < len; k += 32) m = fmaxf(m, Srow[k]);
    #pragma unroll
    for (int o = 16; o; o >>= 1) m = fmaxf(m, __shfl_xor_sync(0xFFFFFFFFu, m, o));
    float ssum = 0.0f;
    for (int k = lane; k < len; k += 32) ssum += expf(Srow[k] - m);
    #pragma unroll
    for (int o = 16; o; o >>= 1) ssum += __shfl_xor_sync(0xFFFFFFFFu, ssum, o);
    float inv = 1.0f / ssum;
    for (int k = lane; k < len; k += 32)
        g_Ph16[base + k] = __float2half_rn(expf(Srow[k] - m) * inv);
    int end = ((q >> 7) + 1) << 7;
    for (int k = q + 1 + lane; k < end; k += 32)
        g_Ph16[base + k] = __float2half(0.0f);
}

// ---------------------------------------------------------------- PV (fp16 single-pass)
__global__ void __launch_bounds__(256) k_pv_mma(float* __restrict__ out) {
    int et = blockIdx.x, qt = 7 - blockIdx.y, bh = blockIdx.z;  // heavy first
    extern __shared__ char smraw[];
    StageV* stg = reinterpret_cast<StageV*>(smraw);
    int tid = threadIdx.x, wid = tid >> 5, lane = tid & 31;
    int wm = (wid >> 2) * 64, wn = (wid & 3) * 32;
    int gr = lane >> 2, t4 = lane & 3;
    int q0 = qt * 128, e0 = et * 128;
    const __half* Ag = g_Ph16 + (size_t)bh * LSEQ * LSEQ + (size_t)q0 * LSEQ;
    const __half* Bg = g_VT16 + ((size_t)bh * DIM + e0) * LSEQ;
    int nst = (qt + 1) * 4;

    float acc[4][4][4] = {};

    #define LDSTV(ST, K0) do {                                                  \
        int _r = tid >> 2, _c = (tid & 3) * 8;                                  \
        cp16(&(ST).Ah[_r][_c],      Ag + (size_t)_r * LSEQ + (K0) + _c);        \
        cp16(&(ST).Ah[_r + 64][_c], Ag + (size_t)(_r + 64) * LSEQ + (K0) + _c); \
        cp16(&(ST).Bh[_r][_c],      Bg + (size_t)_r * LSEQ + (K0) + _c);        \
        cp16(&(ST).Bh[_r + 64][_c], Bg + (size_t)(_r + 64) * LSEQ + (K0) + _c); \
        CP_COMMIT();                                                            \
    } while (0)

    LDSTV(stg[0], 0);

    for (int c = 0; c < nst; c++) {
        if (c + 1 < nst) { LDSTV(stg[(c + 1) & 1], (c + 1) * 32); CP_WAIT1(); }
        else             { CP_WAIT0(); }
        __syncthreads();
        StageV& s = stg[c & 1];
        #pragma unroll
        for (int kk = 0; kk < 32; kk += 16) {
            int kabs = c * 32 + kk;
            uint32_t Af[4][4], Bf[4][2];
            bool live[4];
            #pragma unroll
            for (int mt = 0; mt < 4; mt++) {
                live[mt] = (q0 + wm + mt * 16 + 15) >= kabs;   // P rows nonzero?
                if (live[mt]) {
                    int r = wm + mt * 16 + gr, cc = kk + 2 * t4;
                    Af[mt][0] = *(const uint32_t*)&s.Ah[r][cc];
                    Af[mt][1] = *(const uint32_t*)&s.Ah[r + 8][cc];
                    Af[mt][2] = *(const uint32_t*)&s.Ah[r][cc + 8];
                    Af[mt][3] = *(const uint32_t*)&s.Ah[r + 8][cc + 8];
                }
            }
            #pragma unroll
            for (int nt = 0; nt < 4; nt++) {
                int n = wn + nt * 8 + gr, cc = kk + 2 * t4;
                Bf[nt][0] = *(const uint32_t*)&s.Bh[n][cc];
                Bf[nt][1] = *(const uint32_t*)&s.Bh[n][cc + 8];
            }
            #pragma unroll
            for (int mt = 0; mt < 4; mt++)
                if (live[mt])
                    #pragma unroll
                    for (int nt = 0; nt < 4; nt++)
                        MMAH(acc[mt][nt], Af[mt], Bf[nt]);
        }
        __syncthreads();
    }

    float* O = out + ((size_t)bh * LSEQ + q0) * DIM + e0;
    #pragma unroll
    for (int mt = 0; mt < 4; mt++)
        #pragma unroll
        for (int nt = 0; nt < 4; nt++)
            #pragma unroll
            for (int half = 0; half < 2; half++) {
                int r = wm + mt * 16 + gr + half * 8;
                int c = wn + nt * 8 + 2 * t4;
                float2 v = make_float2(acc[mt][nt][half * 2],
                                       acc[mt][nt][half * 2 + 1]);
                *(float2*)&O[(size_t)r * DIM + c] = v;
            }
}

// ---------------------------------------------------------------- equivariant
__global__ void k_equiv(const float* __restrict__ xi, float* __restrict__ out) {
    __shared__ float xs[LSEQ][3];
    int bh = blockIdx.y;
    int tid = threadIdx.x;
    const float inv23 = 0.0021544346900318843f;

    for (int l = tid; l < LSEQ; l += 128) {
        float fl = (float)l;
        const float* xr = xi + ((size_t)bh * LSEQ + l) * 3;
        xs[l][0] = xr[0] + sinf(fl);
        xs[l][1] = xr[1] + cosf(fl);
        xs[l][2] = xr[2] + sinf(fl * inv23);
    }
    __syncthreads();

    int q = blockIdx.x * 128 + tid;
    float qx = xs[q][0], qy = xs[q][1], qz = xs[q][2];
    float m = -1e30f, denom = 0.0f, wn = 0.0f;
    float n0 = 0.0f, n1 = 0.0f, n2 = 0.0f;
    for (int k = 0; k <= q; k++) {
        float dx = qx - xs[k][0], dy = qy - xs[k][1], dz = qz - xs[k][2];
        float sq = dx * dx + dy * dy + dz * dz;
        if (sq > m) {
            float sc = expf(m - sq);
            denom *= sc; wn *= sc; n0 *= sc; n1 *= sc; n2 *= sc;
            m = sq;
        }
        float e = expf(sq - m);
        denom += e;
        if (k != q) { wn += e; n0 += e * xs[k][0]; n1 += e * xs[k][1]; n2 += e * xs[k][2]; }
    }
    float invd = 1.0f / denom;
    float bw = 0.5f * wn * invd;
    float* o = out + X_OFF + ((size_t)bh * LSEQ + q) * 3;
    o[0] = qx + 0.5f * n0 * invd - bw * qx;
    o[1] = qy + 0.5f * n1 * invd - bw * qy;
    o[2] = qz + 0.5f * n2 * invd - bw * qz;
}

// ---------------------------------------------------------------- edge
__global__ void k_edge(const float* __restrict__ edge, float* __restrict__ out) {
    int idx = blockIdx.x * 256 + threadIdx.x;
    int c = idx % EDGE_C;
    int l = (idx / EDGE_C) & (LSEQ - 1);
    float expo = (float)(c & ~1) * (1.0f / (float)EDGE_C);
    float ang = (float)l / powf(KAPPA, expo);
    float pe = (c & 1) ? cosf(ang) : sinf(ang);
    out[E_OFF + idx] = edge[idx] + pe;
}

// ----------------------------------------------------------------------------
extern "C" void kernel_launch(void* const* d_in, const int* in_sizes, int n_in,
                              void* d_out, int out_size) {
    const float* theta = (const float*)d_in[0];
    const float* xi    = (const float*)d_in[1];
    const float* edge  = (const float*)d_in[2];
    const float* Wq    = (const float*)d_in[3];
    const float* Wk    = (const float*)d_in[4];
    const float* Wv    = (const float*)d_in[5];
    float* out = (float*)d_out;

    static bool attr_done = false;
    if (!attr_done) {
        cudaFuncSetAttribute(k_qkv_mma,    cudaFuncAttributeMaxDynamicSharedMemorySize, (int)SMEM_G2);
        cudaFuncSetAttribute(k_scores_mma, cudaFuncAttributeMaxDynamicSharedMemorySize, (int)SMEM_G2);
        cudaFuncSetAttribute(k_pv_mma,     cudaFuncAttributeMaxDynamicSharedMemorySize, (int)SMEM_PV);
        attr_done = true;
    }

    k_prep_w<<<(3 * DIM * DIM) / 256, 256>>>(Wq, Wk, Wv);
    k_theta_pe<<<H_ELEMS / 256, 256>>>(theta);
    k_qkv_mma<<<dim3(2, 256, 3), 256, SMEM_G2>>>();
    k_vt<<<dim3(32, 8, 32), dim3(32, 8)>>>();
    k_scores_mma<<<dim3(8, 8, BH), 256, SMEM_G2>>>();
    k_softmax<<<(BH * LSEQ) / 8, 256>>>();
    k_pv_mma<<<dim3(2, 8, BH), 256, SMEM_PV>>>(out);
    k_equiv<<<dim3(8, BH), 128>>>(xi, out);
    k_edge<<<E_ELEMS / 256, 256>>>(edge, out);
}